// round 4
// baseline (speedup 1.0000x reference)
#include <cuda_runtime.h>
#include <math.h>

// Problem constants
#define NROWS 8192      // 2B rows
#define HALF  4096
#define DIM   2048      // embed dim
#define PD    256       // projection dim
#define NT    64        // 8192/128 tiles per dim

// Scratch (device globals; no allocation allowed)
__device__ float g_norm[NROWS * PD];       // out_head, then normalized in place (8 MB)
__device__ float g_part[NT * NROWS];       // per-tile partial neg sums (2 MB)
__device__ float g_neg[NROWS];
__device__ float g_pos[HALF];

// ---------------------------------------------------------------------------
// K1: C[8192,256] = A[8192,2048] @ W[2048,256] + b   (fp32 tiled GEMM)
// BM=64, BN=128, BK=16, 256 threads, 4x8 microtile, vectorized LDS
// ---------------------------------------------------------------------------
__global__ void __launch_bounds__(256) k_gemm1(
    const float* __restrict__ A, const float* __restrict__ W,
    const float* __restrict__ b, float* __restrict__ C)
{
    __shared__ float As[16][68];    // k-major, 68*4=272B row, 16B-aligned cols
    __shared__ float Ws[16][128];

    const int bx = blockIdx.x;           // 0..127 (row tiles)
    const int by = blockIdx.y;           // 0..1   (col tiles)
    const int tid = threadIdx.x;
    const int tx = tid & 15, ty = tid >> 4;
    const int row0 = bx * 64, col0 = by * 128;

    float acc[4][8];
    #pragma unroll
    for (int i = 0; i < 4; i++)
        #pragma unroll
        for (int j = 0; j < 8; j++) acc[i][j] = 0.f;

    for (int kk = 0; kk < DIM; kk += 16) {
        // A tile: 64x16 = 256 float4, 1 per thread (store transposed k-major)
        {
            int r = tid >> 2, q = tid & 3;
            float4 v = *(const float4*)&A[(size_t)(row0 + r) * DIM + kk + q * 4];
            As[q * 4 + 0][r] = v.x; As[q * 4 + 1][r] = v.y;
            As[q * 4 + 2][r] = v.z; As[q * 4 + 3][r] = v.w;
        }
        // W tile: 16x128 = 512 float4, 2 per thread (natural layout)
        #pragma unroll
        for (int i = 0; i < 2; i++) {
            int idx = tid + i * 256;
            int r = idx >> 5, c = idx & 31;
            *(float4*)&Ws[r][c * 4] =
                *(const float4*)&W[(size_t)(kk + r) * PD + col0 + c * 4];
        }
        __syncthreads();
        #pragma unroll
        for (int k = 0; k < 16; k++) {
            float4 av = *(const float4*)&As[k][ty * 4];
            float4 w0 = *(const float4*)&Ws[k][tx * 8];
            float4 w1 = *(const float4*)&Ws[k][tx * 8 + 4];
            float a[4] = {av.x, av.y, av.z, av.w};
            float w[8] = {w0.x, w0.y, w0.z, w0.w, w1.x, w1.y, w1.z, w1.w};
            #pragma unroll
            for (int i = 0; i < 4; i++)
                #pragma unroll
                for (int j = 0; j < 8; j++) acc[i][j] += a[i] * w[j];
        }
        __syncthreads();
    }
    float4 b0 = *(const float4*)&b[col0 + tx * 8];
    float4 b1 = *(const float4*)&b[col0 + tx * 8 + 4];
    #pragma unroll
    for (int i = 0; i < 4; i++) {
        int r = row0 + ty * 4 + i;
        float4 o0 = make_float4(acc[i][0] + b0.x, acc[i][1] + b0.y,
                                acc[i][2] + b0.z, acc[i][3] + b0.w);
        float4 o1 = make_float4(acc[i][4] + b1.x, acc[i][5] + b1.y,
                                acc[i][6] + b1.z, acc[i][7] + b1.w);
        *(float4*)&C[(size_t)r * PD + col0 + tx * 8]     = o0;
        *(float4*)&C[(size_t)r * PD + col0 + tx * 8 + 4] = o1;
    }
}

// ---------------------------------------------------------------------------
// K2: row L2-normalize in place (x / max(||x||, 1e-12)). One block per row.
// ---------------------------------------------------------------------------
__global__ void __launch_bounds__(256) k_norm(float* __restrict__ X)
{
    __shared__ float sh[256];
    float* x = X + (size_t)blockIdx.x * PD;
    float v = x[threadIdx.x];
    sh[threadIdx.x] = v * v;
    __syncthreads();
    #pragma unroll
    for (int o = 128; o > 0; o >>= 1) {
        if (threadIdx.x < o) sh[threadIdx.x] += sh[threadIdx.x + o];
        __syncthreads();
    }
    float inv = 1.0f / fmaxf(sqrtf(sh[0]), 1e-12f);
    x[threadIdx.x] = v * inv;
}

// ---------------------------------------------------------------------------
// K3: pos dots d_i = n_i . n_{i+4096}   (warp per i)
// ---------------------------------------------------------------------------
__global__ void __launch_bounds__(256) k_pos(const float* __restrict__ Nm,
                                             float* __restrict__ pos)
{
    int w = (blockIdx.x * blockDim.x + threadIdx.x) >> 5;
    int lane = threadIdx.x & 31;
    if (w >= HALF) return;
    const float* a = Nm + (size_t)w * PD;
    const float* c = Nm + (size_t)(w + HALF) * PD;
    float s = 0.f;
    #pragma unroll
    for (int k = lane; k < PD; k += 32) s += a[k] * c[k];
    #pragma unroll
    for (int o = 16; o > 0; o >>= 1) s += __shfl_down_sync(0xffffffff, s, o);
    if (lane == 0) pos[w] = s;
}

// ---------------------------------------------------------------------------
// K4: symmetric sim tiles. Block handles tile (bi,bj), bi<=bj, 128x128x256.
// Vectorized LDS.128 inner loop. Epilogue: exp(10*sim) w/ diagonal masked,
// row-sums -> g_part[bj], col-sums -> g_part[bi]. One writer per slot.
// ---------------------------------------------------------------------------
__global__ void __launch_bounds__(256) k_sim(const float* __restrict__ Nm,
                                             float* __restrict__ part)
{
    // linear block -> (bi,bj) upper triangle incl diagonal
    int L = blockIdx.x;
    int bi = 0, rem = L;
    while (rem >= NT - bi) { rem -= NT - bi; bi++; }
    int bj = bi + rem;

    __shared__ float As[32][132];   // 132*4=528B row, 16B-aligned float4 cols
    __shared__ float Bs[32][132];
    __shared__ float red[128][17];

    const int tid = threadIdx.x;
    const int tx = tid & 15, ty = tid >> 4;
    const int ro = bi * 128, co = bj * 128;

    float acc[8][8];
    #pragma unroll
    for (int i = 0; i < 8; i++)
        #pragma unroll
        for (int j = 0; j < 8; j++) acc[i][j] = 0.f;

    for (int kk = 0; kk < PD; kk += 32) {
        #pragma unroll
        for (int i = 0; i < 4; i++) {
            int idx = tid + i * 256;
            int r = idx >> 3, q = idx & 7;
            float4 v = *(const float4*)&Nm[(size_t)(ro + r) * PD + kk + q * 4];
            As[q * 4 + 0][r] = v.x; As[q * 4 + 1][r] = v.y;
            As[q * 4 + 2][r] = v.z; As[q * 4 + 3][r] = v.w;
            float4 u = *(const float4*)&Nm[(size_t)(co + r) * PD + kk + q * 4];
            Bs[q * 4 + 0][r] = u.x; Bs[q * 4 + 1][r] = u.y;
            Bs[q * 4 + 2][r] = u.z; Bs[q * 4 + 3][r] = u.w;
        }
        __syncthreads();
        #pragma unroll
        for (int k = 0; k < 32; k++) {
            float4 a0 = *(const float4*)&As[k][ty * 8];
            float4 a1 = *(const float4*)&As[k][ty * 8 + 4];
            float4 v0 = *(const float4*)&Bs[k][tx * 8];
            float4 v1 = *(const float4*)&Bs[k][tx * 8 + 4];
            float a[8]  = {a0.x, a0.y, a0.z, a0.w, a1.x, a1.y, a1.z, a1.w};
            float bv[8] = {v0.x, v0.y, v0.z, v0.w, v1.x, v1.y, v1.z, v1.w};
            #pragma unroll
            for (int i = 0; i < 8; i++)
                #pragma unroll
                for (int j = 0; j < 8; j++) acc[i][j] += a[i] * bv[j];
        }
        __syncthreads();
    }

    // epilogue: exp + mask + per-thread row/col partials
    float rs[8], cs[8];
    #pragma unroll
    for (int i = 0; i < 8; i++) { rs[i] = 0.f; cs[i] = 0.f; }
    #pragma unroll
    for (int i = 0; i < 8; i++) {
        int gi = ro + ty * 8 + i;
        #pragma unroll
        for (int j = 0; j < 8; j++) {
            int gj = co + tx * 8 + j;
            float v = (gi == gj) ? 0.0f : __expf(acc[i][j] * 10.0f);
            rs[i] += v;
            cs[j] += v;
        }
    }

    // reduce row sums across the 16 thread-columns
    #pragma unroll
    for (int i = 0; i < 8; i++) red[ty * 8 + i][tx] = rs[i];
    __syncthreads();
    if (tid < 128) {
        float s = 0.f;
        #pragma unroll
        for (int t = 0; t < 16; t++) s += red[tid][t];
        part[(size_t)bj * NROWS + ro + tid] = s;
    }
    __syncthreads();

    if (bi != bj) {
        // reduce col sums across the 16 thread-rows
        #pragma unroll
        for (int j = 0; j < 8; j++) red[tx * 8 + j][ty] = cs[j];
        __syncthreads();
        if (tid < 128) {
            float s = 0.f;
            #pragma unroll
            for (int t = 0; t < 16; t++) s += red[tid][t];
            part[(size_t)bi * NROWS + co + tid] = s;
        }
    }
}

// ---------------------------------------------------------------------------
// K5: neg[i] = sum over 64 slots (fixed order => deterministic)
// ---------------------------------------------------------------------------
__global__ void __launch_bounds__(256) k_neg(const float* __restrict__ part,
                                             float* __restrict__ neg)
{
    int i = blockIdx.x * blockDim.x + threadIdx.x;
    float s = 0.f;
    #pragma unroll
    for (int t = 0; t < NT; t++) s += part[(size_t)t * NROWS + i];
    neg[i] = s;
}

// ---------------------------------------------------------------------------
// K6: loss = (sum log(neg) - 20 * sum pos_d) / 8192
// ---------------------------------------------------------------------------
__global__ void __launch_bounds__(256) k_loss(const float* __restrict__ neg,
                                              const float* __restrict__ pos,
                                              float* __restrict__ out)
{
    __shared__ float sh[256];
    float s = 0.f;
    for (int i = threadIdx.x; i < NROWS; i += 256) s += logf(neg[i]);
    float p = 0.f;
    for (int i = threadIdx.x; i < HALF; i += 256) p += pos[i];

    sh[threadIdx.x] = s;
    __syncthreads();
    #pragma unroll
    for (int o = 128; o > 0; o >>= 1) {
        if (threadIdx.x < o) sh[threadIdx.x] += sh[threadIdx.x + o];
        __syncthreads();
    }
    float sumlog = sh[0];
    __syncthreads();
    sh[threadIdx.x] = p;
    __syncthreads();
    #pragma unroll
    for (int o = 128; o > 0; o >>= 1) {
        if (threadIdx.x < o) sh[threadIdx.x] += sh[threadIdx.x + o];
        __syncthreads();
    }
    if (threadIdx.x == 0)
        out[0] = (sumlog - 20.0f * sh[0]) / (float)NROWS;
}

// ---------------------------------------------------------------------------
extern "C" void kernel_launch(void* const* d_in, const int* in_sizes, int n_in,
                              void* d_out, int out_size)
{
    const float* X = (const float*)d_in[0];  // [8192, 2048]
    const float* W = (const float*)d_in[1];  // [2048, 256]
    const float* b = (const float*)d_in[2];  // [256]
    float* out = (float*)d_out;

    float* nrm;  cudaGetSymbolAddress((void**)&nrm,  g_norm);
    float* part; cudaGetSymbolAddress((void**)&part, g_part);
    float* neg;  cudaGetSymbolAddress((void**)&neg,  g_neg);
    float* pos;  cudaGetSymbolAddress((void**)&pos,  g_pos);

    k_gemm1<<<dim3(128, 2), 256>>>(X, W, b, nrm);
    k_norm<<<NROWS, 256>>>(nrm);
    k_pos<<<512, 256>>>(nrm, pos);
    k_sim<<<NT * (NT + 1) / 2, 256>>>(nrm, part);   // 2080 blocks
    k_neg<<<NROWS / 256, 256>>>(part, neg);
    k_loss<<<1, 256>>>(neg, pos, out);
}

// round 7
// speedup vs baseline: 2.2751x; 2.2751x over previous
#include <cuda_runtime.h>
#include <cuda_bf16.h>
#include <math.h>
#include <cstdint>

// Problem constants
#define NROWS 8192
#define HALF  4096
#define DIM   2048
#define PD    256
#define NT    64        // 8192/128 tiles per dim

// Feature gate: tcgen05 exists only in the arch-specific sm_103a/sm_100a SASS
// pass. The portable compute_103 PTX pass gets a SIMT fallback (never run —
// the loader uses the exact-match cubin).
#if !defined(__CUDA_ARCH__) || defined(__CUDA_ARCH_FEAT_SM103_ALL) || defined(__CUDA_ARCH_FEAT_SM100_ALL)
#define HAS_TCGEN05 1
#else
#define HAS_TCGEN05 0
#endif

// Scratch (device globals; no allocation allowed)
__device__ float         g_norm[NROWS * PD];    // fp32 normalized (8 MB)
__device__ __nv_bfloat16 g_normh[NROWS * PD];   // bf16 normalized (4 MB)
__device__ float         g_part[NT * NROWS];    // per-tile partial sums (2 MB)
__device__ float         g_neg[NROWS];
__device__ float         g_pos[HALF];

// ---------------------------------------------------------------------------
// PTX helpers
// ---------------------------------------------------------------------------
__device__ __forceinline__ uint32_t smem_to_u32(const void* p) {
    uint32_t a;
    asm("{ .reg .u64 t; cvta.to.shared.u64 t, %1; cvt.u32.u64 %0, t; }"
        : "=r"(a) : "l"(p));
    return a;
}
__device__ __forceinline__ uint32_t elect_one_pred() {
    uint32_t pred;
    asm volatile("{\n\t.reg .pred p;\n\telect.sync _|p, 0xFFFFFFFF;\n\t"
                 "selp.b32 %0, 1, 0, p;\n\t}" : "=r"(pred));
    return pred;
}
#define TCGEN05_ALLOC(smem_addr, nCols) \
    asm volatile("tcgen05.alloc.cta_group::1.sync.aligned.shared::cta.b32 [%0], %1;" \
        :: "r"((uint32_t)(smem_addr)), "r"((uint32_t)(nCols)) : "memory")
#define TCGEN05_DEALLOC(tmem, nCols) \
    asm volatile("tcgen05.dealloc.cta_group::1.sync.aligned.b32 %0, %1;" \
        :: "r"(tmem), "r"((uint32_t)(nCols)))
#define TCGEN05_RELINQUISH() \
    asm volatile("tcgen05.relinquish_alloc_permit.cta_group::1.sync.aligned;")
#define TCGEN05_COMMIT(mbar) \
    asm volatile("tcgen05.commit.cta_group::1.mbarrier::arrive::one.shared::cluster.b64 [%0];" \
        :: "r"((uint32_t)(mbar)) : "memory")
#define TCGEN05_WAIT_LD()  asm volatile("tcgen05.wait::ld.sync.aligned;" ::: "memory")
#define TCGEN05_FENCE_BEFORE() asm volatile("tcgen05.fence::before_thread_sync;" ::: "memory")
#define TCGEN05_FENCE_AFTER()  asm volatile("tcgen05.fence::after_thread_sync;" ::: "memory")
#define FENCE_PROXY_ASYNC() asm volatile("fence.proxy.async.shared::cta;" ::: "memory")
#define MBARRIER_INIT(mbar, cnt) \
    asm volatile("mbarrier.init.shared.b64 [%0], %1;" \
        :: "r"((uint32_t)(mbar)), "r"((uint32_t)(cnt)) : "memory")
#define MBARRIER_INVAL(mbar) \
    asm volatile("mbarrier.inval.shared.b64 [%0];" :: "r"((uint32_t)(mbar)) : "memory")
#define MBARRIER_WAIT_PARITY(mbar, par) do {                                     \
    uint32_t _m = (uint32_t)(mbar), _p = (uint32_t)(par), _d;                    \
    asm volatile("{\n\t.reg .pred p;\n\t"                                        \
        "mbarrier.try_wait.parity.acquire.cta.shared::cta.b64 p, [%1], %2;\n\t"  \
        "selp.b32 %0, 1, 0, p;\n\t}" : "=r"(_d) : "r"(_m), "r"(_p) : "memory");  \
    if (!_d) {                                                                   \
        asm volatile("{\n\t.reg .pred P1;\n\tWL_%=:\n\t"                         \
            "mbarrier.try_wait.parity.acquire.cta.shared::cta.b64 P1, [%0], %1, 0x989680;\n\t" \
            "@P1 bra.uni WD_%=;\n\tbra.uni WL_%=;\n\tWD_%=:\n\t}"                \
            :: "r"(_m), "r"(_p) : "memory");                                     \
    } } while (0)
#define TCGEN05_LD_32X32B_X32(r, tmem) \
    asm volatile("tcgen05.ld.sync.aligned.32x32b.x32.b32 " \
        "{%0, %1, %2, %3, %4, %5, %6, %7, %8, %9, %10, %11, %12, %13, %14, %15, " \
        "%16, %17, %18, %19, %20, %21, %22, %23, %24, %25, %26, %27, %28, %29, %30, %31}, [%32];" \
        : "=r"((r)[0]),  "=r"((r)[1]),  "=r"((r)[2]),  "=r"((r)[3]),  \
          "=r"((r)[4]),  "=r"((r)[5]),  "=r"((r)[6]),  "=r"((r)[7]),  \
          "=r"((r)[8]),  "=r"((r)[9]),  "=r"((r)[10]), "=r"((r)[11]), \
          "=r"((r)[12]), "=r"((r)[13]), "=r"((r)[14]), "=r"((r)[15]), \
          "=r"((r)[16]), "=r"((r)[17]), "=r"((r)[18]), "=r"((r)[19]), \
          "=r"((r)[20]), "=r"((r)[21]), "=r"((r)[22]), "=r"((r)[23]), \
          "=r"((r)[24]), "=r"((r)[25]), "=r"((r)[26]), "=r"((r)[27]), \
          "=r"((r)[28]), "=r"((r)[29]), "=r"((r)[30]), "=r"((r)[31]) \
        : "r"(tmem))
// SW128 descriptor: layout=2, version=1(Blackwell), SBO=64, LBO=1
#define SMEM_DESC_BASE_SW128 \
    ((uint64_t(2) << 61) | (uint64_t(1) << 46) | (uint64_t(64) << 32) | (uint64_t(1) << 16))
#define MAKE_SMEM_DESC(addr) (SMEM_DESC_BASE_SW128 | ((uint64_t)((addr) >> 4) & 0x3FFF))
#define SW128(off) ((off) ^ (((off) >> 3) & 0x70))

#if HAS_TCGEN05
// SS-mode bf16 MMA, cta_group::1
__device__ __forceinline__ void mma_f16_ss(uint32_t d_tmem, uint64_t a_desc,
                                           uint64_t b_desc, uint32_t idesc,
                                           bool accum) {
    uint32_t en = accum ? 1u : 0u;
    asm volatile(
        "{\n\t.reg .pred p;\n\tsetp.ne.u32 p, %5, 0;\n\t"
        "tcgen05.mma.cta_group::1.kind::f16 [%0], %1, %2, %3, {%4, %4, %4, %4}, p;\n\t}"
        :: "r"(d_tmem), "l"(a_desc), "l"(b_desc), "r"(idesc), "r"(0u), "r"(en)
        : "memory");
}
#endif

// idesc: dtype F32, atype/btype BF16, N=128, M=128
#define SIM_IDESC ((1u << 4) | (1u << 7) | (1u << 10) | ((128u / 8u) << 17) | ((128u / 16u) << 24))

// ---------------------------------------------------------------------------
// K1: C[8192,256] = A[8192,2048] @ W[2048,256] + b   (fp32, round-1 config)
// ---------------------------------------------------------------------------
__global__ void __launch_bounds__(256) k_gemm1(
    const float* __restrict__ A, const float* __restrict__ W,
    const float* __restrict__ b, float* __restrict__ C)
{
    __shared__ float As[16][132];
    __shared__ float Ws[16][64];

    const int bx = blockIdx.x, by = blockIdx.y;
    const int tid = threadIdx.x;
    const int tx = tid & 15, ty = tid >> 4;
    const int row0 = bx * 128, col0 = by * 64;

    float acc[8][4];
    #pragma unroll
    for (int i = 0; i < 8; i++)
        #pragma unroll
        for (int j = 0; j < 4; j++) acc[i][j] = 0.f;

    for (int kk = 0; kk < DIM; kk += 16) {
        #pragma unroll
        for (int i = 0; i < 2; i++) {
            int idx = tid + i * 256;
            int r = idx >> 2, q = idx & 3;
            float4 v = *(const float4*)&A[(size_t)(row0 + r) * DIM + kk + q * 4];
            As[q * 4 + 0][r] = v.x; As[q * 4 + 1][r] = v.y;
            As[q * 4 + 2][r] = v.z; As[q * 4 + 3][r] = v.w;
        }
        {
            int r = tid >> 4, q = tid & 15;
            float4 v = *(const float4*)&W[(size_t)(kk + r) * PD + col0 + q * 4];
            *(float4*)&Ws[r][q * 4] = v;
        }
        __syncthreads();
        #pragma unroll
        for (int k = 0; k < 16; k++) {
            float4 a0 = *(const float4*)&As[k][ty * 8];
            float4 a1 = *(const float4*)&As[k][ty * 8 + 4];
            float4 w0 = *(const float4*)&Ws[k][tx * 4];
            float a[8] = {a0.x, a0.y, a0.z, a0.w, a1.x, a1.y, a1.z, a1.w};
            float w[4] = {w0.x, w0.y, w0.z, w0.w};
            #pragma unroll
            for (int i = 0; i < 8; i++)
                #pragma unroll
                for (int j = 0; j < 4; j++) acc[i][j] += a[i] * w[j];
        }
        __syncthreads();
    }
    #pragma unroll
    for (int i = 0; i < 8; i++) {
        int r = row0 + ty * 8 + i;
        #pragma unroll
        for (int j = 0; j < 4; j++) {
            int c = col0 + tx * 4 + j;
            C[(size_t)r * PD + c] = acc[i][j] + b[c];
        }
    }
}

// ---------------------------------------------------------------------------
// K2: row L2-normalize; write fp32 (for pos) and bf16 (for tcgen05 sim)
// ---------------------------------------------------------------------------
__global__ void __launch_bounds__(256) k_norm(float* __restrict__ X,
                                              __nv_bfloat16* __restrict__ Xh)
{
    __shared__ float sh[256];
    size_t base = (size_t)blockIdx.x * PD;
    float v = X[base + threadIdx.x];
    sh[threadIdx.x] = v * v;
    __syncthreads();
    #pragma unroll
    for (int o = 128; o > 0; o >>= 1) {
        if (threadIdx.x < o) sh[threadIdx.x] += sh[threadIdx.x + o];
        __syncthreads();
    }
    float inv = 1.0f / fmaxf(sqrtf(sh[0]), 1e-12f);
    float n = v * inv;
    X[base + threadIdx.x]  = n;
    Xh[base + threadIdx.x] = __float2bfloat16(n);
}

// ---------------------------------------------------------------------------
// K3: pos dots d_i = n_i . n_{i+4096} (fp32, warp per i)
// ---------------------------------------------------------------------------
__global__ void __launch_bounds__(256) k_pos(const float* __restrict__ Nm,
                                             float* __restrict__ pos)
{
    int w = (blockIdx.x * blockDim.x + threadIdx.x) >> 5;
    int lane = threadIdx.x & 31;
    if (w >= HALF) return;
    const float* a = Nm + (size_t)w * PD;
    const float* c = Nm + (size_t)(w + HALF) * PD;
    float s = 0.f;
    #pragma unroll
    for (int k = lane; k < PD; k += 32) s += a[k] * c[k];
    #pragma unroll
    for (int o = 16; o > 0; o >>= 1) s += __shfl_down_sync(0xffffffff, s, o);
    if (lane == 0) pos[w] = s;
}

// ---------------------------------------------------------------------------
// K4: tcgen05 bf16 sim tiles, SYMMETRIC grid (2080 upper-tri tiles).
// Block (bi,bj): 128x128 sim tile over K=256 in TMEM. Epilogue: e=exp(10*sim)
// w/ diag mask; row sums (per-lane) -> part[bj][ro+tid]; exp tile staged to
// SMEM for col sums -> part[bi][co+tid] (off-diag only). One writer per slot.
// SMEM: ctrl | A tile 64KB | B tile 64KB | E tile 128x132 f32 (67.6KB)
// ---------------------------------------------------------------------------
__global__ void __launch_bounds__(128, 1) k_sim_tc(
    const __nv_bfloat16* __restrict__ Nh, float* __restrict__ part)
{
    extern __shared__ __align__(16) char smem[];
    const int tid = threadIdx.x;

    // linear block -> (bi,bj) upper triangle incl diagonal
    int L = blockIdx.x;
    int bi = 0, rem = L;
    while (rem >= NT - bi) { rem -= NT - bi; bi++; }
    int bj = bi + rem;
    const int ro = bi * 128, co = bj * 128;

#if HAS_TCGEN05
    const uint32_t smem_base = smem_to_u32(smem);
    const uint32_t aoff = ((smem_base + 1024 + 1023) & ~1023u) - smem_base;
    const uint32_t A_OFF = aoff;
    const uint32_t B_OFF = aoff + 65536;
    const uint32_t E_OFF = aoff + 131072;
    const uint32_t TPTR = 0, MBAR = 16;

    if (tid < 32) {
        TCGEN05_ALLOC(smem_base + TPTR, 128);
        TCGEN05_RELINQUISH();
    }
    if (tid == 0) MBARRIER_INIT(smem_base + MBAR, 1);
    __syncthreads();
    uint32_t tmem;
    asm volatile("ld.shared.b32 %0, [%1];" : "=r"(tmem) : "r"(smem_base + TPTR));

    // Load A (rows ro..) and B (rows co..), K-major SW128 blocked atoms:
    // atom = 8 rows x 64 bf16 (1024B); 16 atom-rows x 4 atom-cols;
    // atom_off = atom_row + atom_col*16.
    #pragma unroll
    for (int it = 0; it < 32; it++) {
        int idx = tid + it * 128;           // 0..4095
        int r = idx >> 5, q = idx & 31;     // row 0..127, 16B-unit 0..31
        uint32_t byte_off = (uint32_t)((r >> 3) + ((q >> 3) << 4)) * 1024u
                          + (uint32_t)(r & 7) * 128u + (uint32_t)(q & 7) * 16u;
        uint32_t sw = SW128(byte_off);
        const uint4* pa = (const uint4*)(Nh + (size_t)(ro + r) * PD);
        const uint4* pb = (const uint4*)(Nh + (size_t)(co + r) * PD);
        *(uint4*)(smem + A_OFF + sw) = pa[q];
        *(uint4*)(smem + B_OFF + sw) = pb[q];
    }
    __syncthreads();
    FENCE_PROXY_ASYNC();

    // 16 chained K=16 MMAs. Desc offset (16B units): (s/4)*1024 + (s%4)*2.
    if (tid < 32) {
        uint64_t a_base = MAKE_SMEM_DESC(smem_base + A_OFF);
        uint64_t b_base = MAKE_SMEM_DESC(smem_base + B_OFF);
        if (elect_one_pred()) {
            #pragma unroll
            for (int s = 0; s < 16; s++) {
                uint64_t off = (uint64_t)((s >> 2) * 1024 + (s & 3) * 2);
                mma_f16_ss(tmem, a_base + off, b_base + off, SIM_IDESC, s > 0);
            }
            TCGEN05_COMMIT(smem_base + MBAR);
        }
    }

    MBARRIER_WAIT_PARITY(smem_base + MBAR, 0);
    TCGEN05_FENCE_AFTER();

    // Epilogue: thread tid owns sim row tid (LD is subpartition-relative;
    // warp w lanes map to rows 32w..32w+31 => row == tid).
    const int gi = ro + tid;
    const bool offdiag = (bi != bj);
    float* E = (float*)(smem + E_OFF);
    float rowsum = 0.f;
    #pragma unroll
    for (int c4 = 0; c4 < 4; c4++) {
        uint32_t r[32];
        TCGEN05_LD_32X32B_X32(r, tmem + c4 * 32);
        TCGEN05_WAIT_LD();
        #pragma unroll
        for (int jq = 0; jq < 8; jq++) {
            float4 ev;
            #pragma unroll
            for (int m = 0; m < 4; m++) {
                int j = jq * 4 + m;
                int gj = co + c4 * 32 + j;
                float e = __expf(10.0f * __uint_as_float(r[j]));
                e = (gi == gj) ? 0.0f : e;
                ((float*)&ev)[m] = e;
                rowsum += e;
            }
            if (offdiag)
                *(float4*)&E[tid * 132 + c4 * 32 + jq * 4] = ev;
        }
    }
    TCGEN05_FENCE_BEFORE();
    part[(size_t)bj * NROWS + ro + tid] = rowsum;

    if (offdiag) {
        __syncthreads();
        float cs = 0.f;
        #pragma unroll 8
        for (int r = 0; r < 128; r++) cs += E[r * 132 + tid];
        part[(size_t)bi * NROWS + co + tid] = cs;
    }

    __syncthreads();
    if (tid == 0) MBARRIER_INVAL(smem_base + MBAR);
    __syncthreads();
    if (tid < 32) TCGEN05_DEALLOC(tmem, 128);
#else
    // SIMT fallback for the portable-PTX pass (never executed on GB300:
    // the sm_103a cubin is exact-match loaded). Correct but slow.
    float* E = (float*)smem;   // 128 x 132 exp tile
    const int gi = ro + tid;
    const bool offdiag = (bi != bj);
    const __nv_bfloat16* arow = Nh + (size_t)gi * PD;
    float rowsum = 0.f;
    for (int j = 0; j < 128; j++) {
        const __nv_bfloat16* brow = Nh + (size_t)(co + j) * PD;
        float s = 0.f;
        for (int k = 0; k < PD; k++)
            s += __bfloat162float(arow[k]) * __bfloat162float(brow[k]);
        float e = (gi == co + j) ? 0.0f : __expf(10.0f * s);
        rowsum += e;
        E[tid * 132 + j] = e;
    }
    part[(size_t)bj * NROWS + ro + tid] = rowsum;
    if (offdiag) {
        __syncthreads();
        float cs = 0.f;
        for (int r = 0; r < 128; r++) cs += E[r * 132 + tid];
        part[(size_t)bi * NROWS + co + tid] = cs;
    }
#endif
}

// ---------------------------------------------------------------------------
// K5: neg[i] = sum over 64 slots (fixed order => deterministic)
// ---------------------------------------------------------------------------
__global__ void __launch_bounds__(256) k_neg(const float* __restrict__ part,
                                             float* __restrict__ neg)
{
    int i = blockIdx.x * blockDim.x + threadIdx.x;
    float s = 0.f;
    #pragma unroll
    for (int t = 0; t < NT; t++) s += part[(size_t)t * NROWS + i];
    neg[i] = s;
}

// ---------------------------------------------------------------------------
// K6: loss = (sum log(neg) - 20 * sum pos_d) / 8192
// ---------------------------------------------------------------------------
__global__ void __launch_bounds__(256) k_loss(const float* __restrict__ neg,
                                              const float* __restrict__ pos,
                                              float* __restrict__ out)
{
    __shared__ float sh[256];
    float s = 0.f;
    for (int i = threadIdx.x; i < NROWS; i += 256) s += logf(neg[i]);
    float p = 0.f;
    for (int i = threadIdx.x; i < HALF; i += 256) p += pos[i];

    sh[threadIdx.x] = s;
    __syncthreads();
    #pragma unroll
    for (int o = 128; o > 0; o >>= 1) {
        if (threadIdx.x < o) sh[threadIdx.x] += sh[threadIdx.x + o];
        __syncthreads();
    }
    float sumlog = sh[0];
    __syncthreads();
    sh[threadIdx.x] = p;
    __syncthreads();
    #pragma unroll
    for (int o = 128; o > 0; o >>= 1) {
        if (threadIdx.x < o) sh[threadIdx.x] += sh[threadIdx.x + o];
        __syncthreads();
    }
    if (threadIdx.x == 0)
        out[0] = (sumlog - 20.0f * sh[0]) / (float)NROWS;
}

// ---------------------------------------------------------------------------
extern "C" void kernel_launch(void* const* d_in, const int* in_sizes, int n_in,
                              void* d_out, int out_size)
{
    const float* X = (const float*)d_in[0];  // [8192, 2048]
    const float* W = (const float*)d_in[1];  // [2048, 256]
    const float* b = (const float*)d_in[2];  // [256]
    float* out = (float*)d_out;

    float* nrm;          cudaGetSymbolAddress((void**)&nrm,  g_norm);
    __nv_bfloat16* nrh;  cudaGetSymbolAddress((void**)&nrh,  g_normh);
    float* part;         cudaGetSymbolAddress((void**)&part, g_part);
    float* neg;          cudaGetSymbolAddress((void**)&neg,  g_neg);
    float* pos;          cudaGetSymbolAddress((void**)&pos,  g_pos);

    // ctrl(1024) + align slack(1024) + A(64K) + B(64K) + E(128*132*4)
    const int SIM_SMEM = 2048 + 2 * 65536 + 128 * 132 * 4;   // 200704 B
    cudaFuncSetAttribute(k_sim_tc,
                         cudaFuncAttributeMaxDynamicSharedMemorySize, SIM_SMEM);

    k_gemm1<<<dim3(64, 4), 256>>>(X, W, b, nrm);
    k_norm<<<NROWS, 256>>>(nrm, nrh);
    k_pos<<<512, 256>>>(nrm, pos);
    k_sim_tc<<<NT * (NT + 1) / 2, 128, SIM_SMEM>>>(nrh, part);   // 2080 blocks
    k_neg<<<NROWS / 256, 256>>>(part, neg);
    k_loss<<<1, 256>>>(neg, pos, out);
}

// round 8
// speedup vs baseline: 5.2194x; 2.2941x over previous
#include <cuda_runtime.h>
#include <cuda_bf16.h>
#include <math.h>
#include <cstdint>

// Problem constants
#define NROWS 8192
#define HALF  4096
#define DIM   2048
#define PD    256
#define NT    64        // 8192/128 tiles per dim

// Feature gate: tcgen05 exists only in the arch-specific sm_103a/sm_100a SASS
// pass. The portable compute_103 PTX pass gets a SIMT fallback (never run —
// the loader uses the exact-match cubin).
#if !defined(__CUDA_ARCH__) || defined(__CUDA_ARCH_FEAT_SM103_ALL) || defined(__CUDA_ARCH_FEAT_SM100_ALL)
#define HAS_TCGEN05 1
#else
#define HAS_TCGEN05 0
#endif

// Scratch (device globals; no allocation allowed)
__device__ float         g_norm[NROWS * PD];    // fp32 normalized (8 MB)
__device__ __nv_bfloat16 g_normh[NROWS * PD];   // bf16 normalized (4 MB)
__device__ __nv_bfloat16 g_Wt[PD * DIM];        // W^T bf16 [256,2048] (1 MB)
__device__ float         g_part[NT * NROWS];    // per-tile partial sums (2 MB)
__device__ float         g_neg[NROWS];
__device__ float         g_pos[HALF];

// ---------------------------------------------------------------------------
// PTX helpers
// ---------------------------------------------------------------------------
__device__ __forceinline__ uint32_t smem_to_u32(const void* p) {
    uint32_t a;
    asm("{ .reg .u64 t; cvta.to.shared.u64 t, %1; cvt.u32.u64 %0, t; }"
        : "=r"(a) : "l"(p));
    return a;
}
__device__ __forceinline__ uint32_t elect_one_pred() {
    uint32_t pred;
    asm volatile("{\n\t.reg .pred p;\n\telect.sync _|p, 0xFFFFFFFF;\n\t"
                 "selp.b32 %0, 1, 0, p;\n\t}" : "=r"(pred));
    return pred;
}
#define TCGEN05_ALLOC(smem_addr, nCols) \
    asm volatile("tcgen05.alloc.cta_group::1.sync.aligned.shared::cta.b32 [%0], %1;" \
        :: "r"((uint32_t)(smem_addr)), "r"((uint32_t)(nCols)) : "memory")
#define TCGEN05_DEALLOC(tmem, nCols) \
    asm volatile("tcgen05.dealloc.cta_group::1.sync.aligned.b32 %0, %1;" \
        :: "r"(tmem), "r"((uint32_t)(nCols)))
#define TCGEN05_RELINQUISH() \
    asm volatile("tcgen05.relinquish_alloc_permit.cta_group::1.sync.aligned;")
#define TCGEN05_COMMIT(mbar) \
    asm volatile("tcgen05.commit.cta_group::1.mbarrier::arrive::one.shared::cluster.b64 [%0];" \
        :: "r"((uint32_t)(mbar)) : "memory")
#define TCGEN05_WAIT_LD()  asm volatile("tcgen05.wait::ld.sync.aligned;" ::: "memory")
#define TCGEN05_FENCE_BEFORE() asm volatile("tcgen05.fence::before_thread_sync;" ::: "memory")
#define TCGEN05_FENCE_AFTER()  asm volatile("tcgen05.fence::after_thread_sync;" ::: "memory")
#define FENCE_PROXY_ASYNC() asm volatile("fence.proxy.async.shared::cta;" ::: "memory")
#define MBARRIER_INIT(mbar, cnt) \
    asm volatile("mbarrier.init.shared.b64 [%0], %1;" \
        :: "r"((uint32_t)(mbar)), "r"((uint32_t)(cnt)) : "memory")
#define MBARRIER_INVAL(mbar) \
    asm volatile("mbarrier.inval.shared.b64 [%0];" :: "r"((uint32_t)(mbar)) : "memory")
#define MBARRIER_WAIT_PARITY(mbar, par) do {                                     \
    uint32_t _m = (uint32_t)(mbar), _p = (uint32_t)(par), _d;                    \
    asm volatile("{\n\t.reg .pred p;\n\t"                                        \
        "mbarrier.try_wait.parity.acquire.cta.shared::cta.b64 p, [%1], %2;\n\t"  \
        "selp.b32 %0, 1, 0, p;\n\t}" : "=r"(_d) : "r"(_m), "r"(_p) : "memory");  \
    if (!_d) {                                                                   \
        asm volatile("{\n\t.reg .pred P1;\n\tWL_%=:\n\t"                         \
            "mbarrier.try_wait.parity.acquire.cta.shared::cta.b64 P1, [%0], %1, 0x989680;\n\t" \
            "@P1 bra.uni WD_%=;\n\tbra.uni WL_%=;\n\tWD_%=:\n\t}"                \
            :: "r"(_m), "r"(_p) : "memory");                                     \
    } } while (0)
#define TCGEN05_LD_32X32B_X32(r, tmem) \
    asm volatile("tcgen05.ld.sync.aligned.32x32b.x32.b32 " \
        "{%0, %1, %2, %3, %4, %5, %6, %7, %8, %9, %10, %11, %12, %13, %14, %15, " \
        "%16, %17, %18, %19, %20, %21, %22, %23, %24, %25, %26, %27, %28, %29, %30, %31}, [%32];" \
        : "=r"((r)[0]),  "=r"((r)[1]),  "=r"((r)[2]),  "=r"((r)[3]),  \
          "=r"((r)[4]),  "=r"((r)[5]),  "=r"((r)[6]),  "=r"((r)[7]),  \
          "=r"((r)[8]),  "=r"((r)[9]),  "=r"((r)[10]), "=r"((r)[11]), \
          "=r"((r)[12]), "=r"((r)[13]), "=r"((r)[14]), "=r"((r)[15]), \
          "=r"((r)[16]), "=r"((r)[17]), "=r"((r)[18]), "=r"((r)[19]), \
          "=r"((r)[20]), "=r"((r)[21]), "=r"((r)[22]), "=r"((r)[23]), \
          "=r"((r)[24]), "=r"((r)[25]), "=r"((r)[26]), "=r"((r)[27]), \
          "=r"((r)[28]), "=r"((r)[29]), "=r"((r)[30]), "=r"((r)[31]) \
        : "r"(tmem))
// SW128 descriptor: layout=2, version=1(Blackwell), SBO=64, LBO=1
#define SMEM_DESC_BASE_SW128 \
    ((uint64_t(2) << 61) | (uint64_t(1) << 46) | (uint64_t(64) << 32) | (uint64_t(1) << 16))
#define MAKE_SMEM_DESC(addr) (SMEM_DESC_BASE_SW128 | ((uint64_t)((addr) >> 4) & 0x3FFF))
#define SW128(off) ((off) ^ (((off) >> 3) & 0x70))

#if HAS_TCGEN05
// SS-mode bf16 MMA, cta_group::1
__device__ __forceinline__ void mma_f16_ss(uint32_t d_tmem, uint64_t a_desc,
                                           uint64_t b_desc, uint32_t idesc,
                                           bool accum) {
    uint32_t en = accum ? 1u : 0u;
    asm volatile(
        "{\n\t.reg .pred p;\n\tsetp.ne.u32 p, %5, 0;\n\t"
        "tcgen05.mma.cta_group::1.kind::f16 [%0], %1, %2, %3, {%4, %4, %4, %4}, p;\n\t}"
        :: "r"(d_tmem), "l"(a_desc), "l"(b_desc), "r"(idesc), "r"(0u), "r"(en)
        : "memory");
}
#endif

// idesc: dtype F32, atype/btype BF16, M=128; N parametric
#define SIM_IDESC  ((1u << 4) | (1u << 7) | (1u << 10) | ((128u / 8u) << 17) | ((128u / 16u) << 24))
#define GEMM_IDESC ((1u << 4) | (1u << 7) | (1u << 10) | ((256u / 8u) << 17) | ((128u / 16u) << 24))

// ---------------------------------------------------------------------------
// K0: Wt[256,2048] bf16 = transpose(W[2048,256] fp32). 64x64 tiles.
// ---------------------------------------------------------------------------
__global__ void __launch_bounds__(256) k_prep(const float* __restrict__ W,
                                              __nv_bfloat16* __restrict__ Wt)
{
    __shared__ float S[64][68];
    const int k0 = blockIdx.x * 64, n0 = blockIdx.y * 64;
    const int tid = threadIdx.x;

    #pragma unroll
    for (int i = 0; i < 4; i++) {
        int t = tid + i * 256;            // 0..1023 float4 slots
        int r = t >> 4, c4 = t & 15;
        float4 v = *(const float4*)&W[(size_t)(k0 + r) * PD + n0 + c4 * 4];
        S[r][c4 * 4 + 0] = v.x; S[r][c4 * 4 + 1] = v.y;
        S[r][c4 * 4 + 2] = v.z; S[r][c4 * 4 + 3] = v.w;
    }
    __syncthreads();
    #pragma unroll
    for (int i = 0; i < 2; i++) {
        int u = tid + i * 256;            // 0..511 output 16B units
        int n = u >> 3, ku = u & 7;
        __nv_bfloat162 h[4];
        #pragma unroll
        for (int m = 0; m < 4; m++)
            h[m] = __floats2bfloat162_rn(S[ku * 8 + 2 * m][n], S[ku * 8 + 2 * m + 1][n]);
        *(uint4*)&Wt[(size_t)(n0 + n) * DIM + k0 + ku * 8] = *(uint4*)h;
    }
}

// ---------------------------------------------------------------------------
// K1: tcgen05 GEMM1 + bias + fused L2-normalize.
// Grid 64 CTAs (M tiles of 128), N=256 full. K chunks of 256, 8 chunks,
// 16 chained K=16 MMAs per chunk, per-chunk commit/wait (single buffer).
// Epilogue: two LDTM passes (sumsq; then scale+store fp32 + bf16).
// SMEM: ctrl(1024) | A 64KB (128x256 bf16 SW128) | B 128KB (256x256 bf16)
// ---------------------------------------------------------------------------
__global__ void __launch_bounds__(256, 1) k_gemm1_tc(
    const float* __restrict__ X, const __nv_bfloat16* __restrict__ Wt,
    const float* __restrict__ b, float* __restrict__ Nm,
    __nv_bfloat16* __restrict__ Nh)
{
    extern __shared__ __align__(16) char smem[];
    __shared__ float s_red[128][2];
    __shared__ float s_bias[256];

    const int tid = threadIdx.x;
    const int row0 = blockIdx.x * 128;
    s_bias[tid] = b[tid];

#if HAS_TCGEN05
    const uint32_t smem_base = smem_to_u32(smem);
    const uint32_t aoff = ((smem_base + 1024 + 1023) & ~1023u) - smem_base;
    const uint32_t A_OFF = aoff;              // 64 KB
    const uint32_t B_OFF = aoff + 65536;      // 128 KB
    const uint32_t TPTR = 0, MBAR = 16;

    if (tid < 32) {
        TCGEN05_ALLOC(smem_base + TPTR, 256);
        TCGEN05_RELINQUISH();
    }
    if (tid == 0) MBARRIER_INIT(smem_base + MBAR, 1);
    __syncthreads();
    uint32_t tmem;
    asm volatile("ld.shared.b32 %0, [%1];" : "=r"(tmem) : "r"(smem_base + TPTR));

    for (int c = 0; c < 8; c++) {
        const int k0 = c * 256;
        // A chunk: 128 rows x 256 cols bf16 (cvt from fp32). 4096 16B units.
        // atom grid: 16 atom-rows x 4 atom-cols; atom_off = arow + acol*16.
        #pragma unroll
        for (int i = 0; i < 16; i++) {
            int u = tid + i * 256;
            int r = u >> 5, q = u & 31;    // q: 16B unit in 512B row
            float4 v0 = *(const float4*)&X[(size_t)(row0 + r) * DIM + k0 + q * 8];
            float4 v1 = *(const float4*)&X[(size_t)(row0 + r) * DIM + k0 + q * 8 + 4];
            __nv_bfloat162 h[4];
            h[0] = __floats2bfloat162_rn(v0.x, v0.y);
            h[1] = __floats2bfloat162_rn(v0.z, v0.w);
            h[2] = __floats2bfloat162_rn(v1.x, v1.y);
            h[3] = __floats2bfloat162_rn(v1.z, v1.w);
            uint32_t byte_off = (uint32_t)((r >> 3) + ((q >> 3) << 4)) * 1024u
                              + (uint32_t)(r & 7) * 128u + (uint32_t)(q & 7) * 16u;
            *(uint4*)(smem + A_OFF + SW128(byte_off)) = *(uint4*)h;
        }
        // B chunk: 256 rows x 256 cols bf16 from Wt. 8192 16B units.
        // atom grid: 32 atom-rows x 4 atom-cols; atom_off = arow + acol*32.
        #pragma unroll
        for (int i = 0; i < 32; i++) {
            int u = tid + i * 256;
            int r = u >> 5, q = u & 31;
            uint4 v = *(const uint4*)&Wt[(size_t)r * DIM + k0 + q * 8];
            uint32_t byte_off = (uint32_t)((r >> 3) + ((q >> 3) << 5)) * 1024u
                              + (uint32_t)(r & 7) * 128u + (uint32_t)(q & 7) * 16u;
            *(uint4*)(smem + B_OFF + SW128(byte_off)) = v;
        }
        __syncthreads();
        FENCE_PROXY_ASYNC();

        if (tid < 32) {
            uint64_t a_base = MAKE_SMEM_DESC(smem_base + A_OFF);
            uint64_t b_base = MAKE_SMEM_DESC(smem_base + B_OFF);
            if (elect_one_pred()) {
                #pragma unroll
                for (int s = 0; s < 16; s++) {
                    uint64_t offA = (uint64_t)((s >> 2) * 1024 + (s & 3) * 2);
                    uint64_t offB = (uint64_t)((s >> 2) * 2048 + (s & 3) * 2);
                    mma_f16_ss(tmem, a_base + offA, b_base + offB, GEMM_IDESC,
                               (c > 0) || (s > 0));
                }
                TCGEN05_COMMIT(smem_base + MBAR);
            }
        }
        MBARRIER_WAIT_PARITY(smem_base + MBAR, c & 1);
        __syncthreads();
    }
    TCGEN05_FENCE_AFTER();

    // Epilogue: warp w -> subpartition w&3 (rows (w&3)*32+lane), col half w>>2.
    const int w = tid >> 5, lane = tid & 31;
    const int row = (w & 3) * 32 + lane;
    const int half = w >> 2;
    const uint32_t tbase = tmem + half * 128;

    // Pass 1: sumsq
    float sumsq = 0.f;
    #pragma unroll
    for (int c4 = 0; c4 < 4; c4++) {
        uint32_t r[32];
        TCGEN05_LD_32X32B_X32(r, tbase + c4 * 32);
        TCGEN05_WAIT_LD();
        #pragma unroll
        for (int j = 0; j < 32; j++) {
            float v = __uint_as_float(r[j]) + s_bias[half * 128 + c4 * 32 + j];
            sumsq += v * v;
        }
    }
    s_red[row][half] = sumsq;
    __syncthreads();
    float inv = 1.0f / fmaxf(sqrtf(s_red[row][0] + s_red[row][1]), 1e-12f);

    // Pass 2: scale + store
    const size_t gbase = (size_t)(row0 + row) * PD + half * 128;
    #pragma unroll
    for (int c4 = 0; c4 < 4; c4++) {
        uint32_t r[32];
        TCGEN05_LD_32X32B_X32(r, tbase + c4 * 32);
        TCGEN05_WAIT_LD();
        float v[32];
        #pragma unroll
        for (int j = 0; j < 32; j++)
            v[j] = (__uint_as_float(r[j]) + s_bias[half * 128 + c4 * 32 + j]) * inv;
        #pragma unroll
        for (int j4 = 0; j4 < 8; j4++)
            *(float4*)&Nm[gbase + c4 * 32 + j4 * 4] =
                make_float4(v[j4 * 4], v[j4 * 4 + 1], v[j4 * 4 + 2], v[j4 * 4 + 3]);
        __nv_bfloat162 hh[16];
        #pragma unroll
        for (int j2 = 0; j2 < 16; j2++)
            hh[j2] = __floats2bfloat162_rn(v[2 * j2], v[2 * j2 + 1]);
        #pragma unroll
        for (int q = 0; q < 4; q++)
            *(uint4*)&Nh[gbase + c4 * 32 + q * 8] = ((uint4*)hh)[q];
    }
    TCGEN05_FENCE_BEFORE();

    __syncthreads();
    if (tid == 0) MBARRIER_INVAL(smem_base + MBAR);
    __syncthreads();
    if (tid < 32) TCGEN05_DEALLOC(tmem, 256);
#else
    // SIMT fallback (never executed on GB300). Two-pass recompute per row.
    const int row = row0 + tid;
    if (tid < 128) {
        float sumsq = 0.f;
        for (int n = 0; n < PD; n++) {
            float s = 0.f;
            for (int k = 0; k < DIM; k++)
                s += X[(size_t)row * DIM + k] * __bfloat162float(Wt[(size_t)n * DIM + k]);
            s += s_bias[n];
            sumsq += s * s;
        }
        float inv = 1.0f / fmaxf(sqrtf(sumsq), 1e-12f);
        for (int n = 0; n < PD; n++) {
            float s = 0.f;
            for (int k = 0; k < DIM; k++)
                s += X[(size_t)row * DIM + k] * __bfloat162float(Wt[(size_t)n * DIM + k]);
            s = (s + s_bias[n]) * inv;
            Nm[(size_t)row * PD + n] = s;
            Nh[(size_t)row * PD + n] = __float2bfloat16(s);
        }
    }
#endif
}

// ---------------------------------------------------------------------------
// K3: pos dots d_i = n_i . n_{i+4096} (fp32, warp per i)
// ---------------------------------------------------------------------------
__global__ void __launch_bounds__(256) k_pos(const float* __restrict__ Nm,
                                             float* __restrict__ pos)
{
    int w = (blockIdx.x * blockDim.x + threadIdx.x) >> 5;
    int lane = threadIdx.x & 31;
    if (w >= HALF) return;
    const float* a = Nm + (size_t)w * PD;
    const float* c = Nm + (size_t)(w + HALF) * PD;
    float s = 0.f;
    #pragma unroll
    for (int k = lane; k < PD; k += 32) s += a[k] * c[k];
    #pragma unroll
    for (int o = 16; o > 0; o >>= 1) s += __shfl_down_sync(0xffffffff, s, o);
    if (lane == 0) pos[w] = s;
}

// ---------------------------------------------------------------------------
// K4: tcgen05 bf16 sim tiles, SYMMETRIC grid (2080 upper-tri tiles).
// (unchanged from round 7 — known good, 76us)
// ---------------------------------------------------------------------------
__global__ void __launch_bounds__(128, 1) k_sim_tc(
    const __nv_bfloat16* __restrict__ Nh, float* __restrict__ part)
{
    extern __shared__ __align__(16) char smem[];
    const int tid = threadIdx.x;

    int L = blockIdx.x;
    int bi = 0, rem = L;
    while (rem >= NT - bi) { rem -= NT - bi; bi++; }
    int bj = bi + rem;
    const int ro = bi * 128, co = bj * 128;

#if HAS_TCGEN05
    const uint32_t smem_base = smem_to_u32(smem);
    const uint32_t aoff = ((smem_base + 1024 + 1023) & ~1023u) - smem_base;
    const uint32_t A_OFF = aoff;
    const uint32_t B_OFF = aoff + 65536;
    const uint32_t E_OFF = aoff + 131072;
    const uint32_t TPTR = 0, MBAR = 16;

    if (tid < 32) {
        TCGEN05_ALLOC(smem_base + TPTR, 128);
        TCGEN05_RELINQUISH();
    }
    if (tid == 0) MBARRIER_INIT(smem_base + MBAR, 1);
    __syncthreads();
    uint32_t tmem;
    asm volatile("ld.shared.b32 %0, [%1];" : "=r"(tmem) : "r"(smem_base + TPTR));

    #pragma unroll
    for (int it = 0; it < 32; it++) {
        int idx = tid + it * 128;
        int r = idx >> 5, q = idx & 31;
        uint32_t byte_off = (uint32_t)((r >> 3) + ((q >> 3) << 4)) * 1024u
                          + (uint32_t)(r & 7) * 128u + (uint32_t)(q & 7) * 16u;
        uint32_t sw = SW128(byte_off);
        const uint4* pa = (const uint4*)(Nh + (size_t)(ro + r) * PD);
        const uint4* pb = (const uint4*)(Nh + (size_t)(co + r) * PD);
        *(uint4*)(smem + A_OFF + sw) = pa[q];
        *(uint4*)(smem + B_OFF + sw) = pb[q];
    }
    __syncthreads();
    FENCE_PROXY_ASYNC();

    if (tid < 32) {
        uint64_t a_base = MAKE_SMEM_DESC(smem_base + A_OFF);
        uint64_t b_base = MAKE_SMEM_DESC(smem_base + B_OFF);
        if (elect_one_pred()) {
            #pragma unroll
            for (int s = 0; s < 16; s++) {
                uint64_t off = (uint64_t)((s >> 2) * 1024 + (s & 3) * 2);
                mma_f16_ss(tmem, a_base + off, b_base + off, SIM_IDESC, s > 0);
            }
            TCGEN05_COMMIT(smem_base + MBAR);
        }
    }

    MBARRIER_WAIT_PARITY(smem_base + MBAR, 0);
    TCGEN05_FENCE_AFTER();

    const int gi = ro + tid;
    const bool offdiag = (bi != bj);
    float* E = (float*)(smem + E_OFF);
    float rowsum = 0.f;
    #pragma unroll
    for (int c4 = 0; c4 < 4; c4++) {
        uint32_t r[32];
        TCGEN05_LD_32X32B_X32(r, tmem + c4 * 32);
        TCGEN05_WAIT_LD();
        #pragma unroll
        for (int jq = 0; jq < 8; jq++) {
            float4 ev;
            #pragma unroll
            for (int m = 0; m < 4; m++) {
                int j = jq * 4 + m;
                int gj = co + c4 * 32 + j;
                float e = __expf(10.0f * __uint_as_float(r[j]));
                e = (gi == gj) ? 0.0f : e;
                ((float*)&ev)[m] = e;
                rowsum += e;
            }
            if (offdiag)
                *(float4*)&E[tid * 132 + c4 * 32 + jq * 4] = ev;
        }
    }
    TCGEN05_FENCE_BEFORE();
    part[(size_t)bj * NROWS + ro + tid] = rowsum;

    if (offdiag) {
        __syncthreads();
        float cs = 0.f;
        #pragma unroll 8
        for (int r = 0; r < 128; r++) cs += E[r * 132 + tid];
        part[(size_t)bi * NROWS + co + tid] = cs;
    }

    __syncthreads();
    if (tid == 0) MBARRIER_INVAL(smem_base + MBAR);
    __syncthreads();
    if (tid < 32) TCGEN05_DEALLOC(tmem, 128);
#else
    float* E = (float*)smem;
    const int gi = ro + tid;
    const bool offdiag = (bi != bj);
    const __nv_bfloat16* arow = Nh + (size_t)gi * PD;
    float rowsum = 0.f;
    for (int j = 0; j < 128; j++) {
        const __nv_bfloat16* brow = Nh + (size_t)(co + j) * PD;
        float s = 0.f;
        for (int k = 0; k < PD; k++)
            s += __bfloat162float(arow[k]) * __bfloat162float(brow[k]);
        float e = (gi == co + j) ? 0.0f : __expf(10.0f * s);
        rowsum += e;
        E[tid * 132 + j] = e;
    }
    part[(size_t)bj * NROWS + ro + tid] = rowsum;
    if (offdiag) {
        __syncthreads();
        float cs = 0.f;
        for (int r = 0; r < 128; r++) cs += E[r * 132 + tid];
        part[(size_t)bi * NROWS + co + tid] = cs;
    }
#endif
}

// ---------------------------------------------------------------------------
// K5: neg[i] = sum over 64 slots (fixed order => deterministic)
// ---------------------------------------------------------------------------
__global__ void __launch_bounds__(256) k_neg(const float* __restrict__ part,
                                             float* __restrict__ neg)
{
    int i = blockIdx.x * blockDim.x + threadIdx.x;
    float s = 0.f;
    #pragma unroll
    for (int t = 0; t < NT; t++) s += part[(size_t)t * NROWS + i];
    neg[i] = s;
}

// ---------------------------------------------------------------------------
// K6: loss = (sum log(neg) - 20 * sum pos_d) / 8192
// ---------------------------------------------------------------------------
__global__ void __launch_bounds__(256) k_loss(const float* __restrict__ neg,
                                              const float* __restrict__ pos,
                                              float* __restrict__ out)
{
    __shared__ float sh[256];
    float s = 0.f;
    for (int i = threadIdx.x; i < NROWS; i += 256) s += logf(neg[i]);
    float p = 0.f;
    for (int i = threadIdx.x; i < HALF; i += 256) p += pos[i];

    sh[threadIdx.x] = s;
    __syncthreads();
    #pragma unroll
    for (int o = 128; o > 0; o >>= 1) {
        if (threadIdx.x < o) sh[threadIdx.x] += sh[threadIdx.x + o];
        __syncthreads();
    }
    float sumlog = sh[0];
    __syncthreads();
    sh[threadIdx.x] = p;
    __syncthreads();
    #pragma unroll
    for (int o = 128; o > 0; o >>= 1) {
        if (threadIdx.x < o) sh[threadIdx.x] += sh[threadIdx.x + o];
        __syncthreads();
    }
    if (threadIdx.x == 0)
        out[0] = (sumlog - 20.0f * sh[0]) / (float)NROWS;
}

// ---------------------------------------------------------------------------
extern "C" void kernel_launch(void* const* d_in, const int* in_sizes, int n_in,
                              void* d_out, int out_size)
{
    const float* X = (const float*)d_in[0];  // [8192, 2048]
    const float* W = (const float*)d_in[1];  // [2048, 256]
    const float* b = (const float*)d_in[2];  // [256]
    float* out = (float*)d_out;

    float* nrm;          cudaGetSymbolAddress((void**)&nrm,  g_norm);
    __nv_bfloat16* nrh;  cudaGetSymbolAddress((void**)&nrh,  g_normh);
    __nv_bfloat16* wt;   cudaGetSymbolAddress((void**)&wt,   g_Wt);
    float* part;         cudaGetSymbolAddress((void**)&part, g_part);
    float* neg;          cudaGetSymbolAddress((void**)&neg,  g_neg);
    float* pos;          cudaGetSymbolAddress((void**)&pos,  g_pos);

    const int SIM_SMEM  = 2048 + 2 * 65536 + 128 * 132 * 4;  // 200704 B
    const int GEMM_SMEM = 2048 + 65536 + 131072;             // 198656 B
    cudaFuncSetAttribute(k_sim_tc,
                         cudaFuncAttributeMaxDynamicSharedMemorySize, SIM_SMEM);
    cudaFuncSetAttribute(k_gemm1_tc,
                         cudaFuncAttributeMaxDynamicSharedMemorySize, GEMM_SMEM);

    k_prep<<<dim3(32, 4), 256>>>(W, wt);
    k_gemm1_tc<<<64, 256, GEMM_SMEM>>>(X, wt, b, nrm, nrh);
    k_pos<<<512, 256>>>(nrm, pos);
    k_sim_tc<<<NT * (NT + 1) / 2, 128, SIM_SMEM>>>(nrh, part);   // 2080 blocks
    k_neg<<<NROWS / 256, 256>>>(part, neg);
    k_loss<<<1, 256>>>(neg, pos, out);
}

// round 9
// speedup vs baseline: 6.7179x; 1.2871x over previous
#include <cuda_runtime.h>
#include <cuda_bf16.h>
#include <math.h>
#include <cstdint>

// Problem constants
#define NROWS 8192
#define HALF  4096
#define DIM   2048
#define PD    256
#define NT    64

// Feature gate: tcgen05 exists only in the arch-specific sm_103a/sm_100a SASS
// pass. The portable compute_103 PTX pass gets a SIMT fallback (never run).
#if !defined(__CUDA_ARCH__) || defined(__CUDA_ARCH_FEAT_SM103_ALL) || defined(__CUDA_ARCH_FEAT_SM100_ALL)
#define HAS_TCGEN05 1
#else
#define HAS_TCGEN05 0
#endif

// Scratch (device globals; no allocation allowed)
__device__ __nv_bfloat16 g_normh[NROWS * PD];   // bf16 normalized (4 MB)
__device__ __nv_bfloat16 g_Wt[PD * DIM];        // W^T bf16 [256,2048] (1 MB)
__device__ float         g_part[2 * NROWS];     // per-col-half row sums
__device__ float         g_pos[HALF];

// ---------------------------------------------------------------------------
// PTX helpers
// ---------------------------------------------------------------------------
__device__ __forceinline__ uint32_t smem_to_u32(const void* p) {
    uint32_t a;
    asm("{ .reg .u64 t; cvta.to.shared.u64 t, %1; cvt.u32.u64 %0, t; }"
        : "=r"(a) : "l"(p));
    return a;
}
__device__ __forceinline__ uint32_t elect_one_pred() {
    uint32_t pred;
    asm volatile("{\n\t.reg .pred p;\n\telect.sync _|p, 0xFFFFFFFF;\n\t"
                 "selp.b32 %0, 1, 0, p;\n\t}" : "=r"(pred));
    return pred;
}
#define TCGEN05_ALLOC(smem_addr, nCols) \
    asm volatile("tcgen05.alloc.cta_group::1.sync.aligned.shared::cta.b32 [%0], %1;" \
        :: "r"((uint32_t)(smem_addr)), "r"((uint32_t)(nCols)) : "memory")
#define TCGEN05_DEALLOC(tmem, nCols) \
    asm volatile("tcgen05.dealloc.cta_group::1.sync.aligned.b32 %0, %1;" \
        :: "r"(tmem), "r"((uint32_t)(nCols)))
#define TCGEN05_RELINQUISH() \
    asm volatile("tcgen05.relinquish_alloc_permit.cta_group::1.sync.aligned;")
#define TCGEN05_COMMIT(mbar) \
    asm volatile("tcgen05.commit.cta_group::1.mbarrier::arrive::one.shared::cluster.b64 [%0];" \
        :: "r"((uint32_t)(mbar)) : "memory")
#define TCGEN05_WAIT_LD()  asm volatile("tcgen05.wait::ld.sync.aligned;" ::: "memory")
#define TCGEN05_FENCE_BEFORE() asm volatile("tcgen05.fence::before_thread_sync;" ::: "memory")
#define TCGEN05_FENCE_AFTER()  asm volatile("tcgen05.fence::after_thread_sync;" ::: "memory")
#define FENCE_PROXY_ASYNC() asm volatile("fence.proxy.async.shared::cta;" ::: "memory")
#define MBARRIER_INIT(mbar, cnt) \
    asm volatile("mbarrier.init.shared.b64 [%0], %1;" \
        :: "r"((uint32_t)(mbar)), "r"((uint32_t)(cnt)) : "memory")
#define MBARRIER_INVAL(mbar) \
    asm volatile("mbarrier.inval.shared.b64 [%0];" :: "r"((uint32_t)(mbar)) : "memory")
#define MBARRIER_WAIT_PARITY(mbar, par) do {                                     \
    uint32_t _m = (uint32_t)(mbar), _p = (uint32_t)(par), _d;                    \
    asm volatile("{\n\t.reg .pred p;\n\t"                                        \
        "mbarrier.try_wait.parity.acquire.cta.shared::cta.b64 p, [%1], %2;\n\t"  \
        "selp.b32 %0, 1, 0, p;\n\t}" : "=r"(_d) : "r"(_m), "r"(_p) : "memory");  \
    if (!_d) {                                                                   \
        asm volatile("{\n\t.reg .pred P1;\n\tWL_%=:\n\t"                         \
            "mbarrier.try_wait.parity.acquire.cta.shared::cta.b64 P1, [%0], %1, 0x989680;\n\t" \
            "@P1 bra.uni WD_%=;\n\tbra.uni WL_%=;\n\tWD_%=:\n\t}"                \
            :: "r"(_m), "r"(_p) : "memory");                                     \
    } } while (0)
#define TCGEN05_LD_32X32B_X32(r, tmem) \
    asm volatile("tcgen05.ld.sync.aligned.32x32b.x32.b32 " \
        "{%0, %1, %2, %3, %4, %5, %6, %7, %8, %9, %10, %11, %12, %13, %14, %15, " \
        "%16, %17, %18, %19, %20, %21, %22, %23, %24, %25, %26, %27, %28, %29, %30, %31}, [%32];" \
        : "=r"((r)[0]),  "=r"((r)[1]),  "=r"((r)[2]),  "=r"((r)[3]),  \
          "=r"((r)[4]),  "=r"((r)[5]),  "=r"((r)[6]),  "=r"((r)[7]),  \
          "=r"((r)[8]),  "=r"((r)[9]),  "=r"((r)[10]), "=r"((r)[11]), \
          "=r"((r)[12]), "=r"((r)[13]), "=r"((r)[14]), "=r"((r)[15]), \
          "=r"((r)[16]), "=r"((r)[17]), "=r"((r)[18]), "=r"((r)[19]), \
          "=r"((r)[20]), "=r"((r)[21]), "=r"((r)[22]), "=r"((r)[23]), \
          "=r"((r)[24]), "=r"((r)[25]), "=r"((r)[26]), "=r"((r)[27]), \
          "=r"((r)[28]), "=r"((r)[29]), "=r"((r)[30]), "=r"((r)[31]) \
        : "r"(tmem))
#define CP_ASYNC16(smem_u32, gptr) \
    asm volatile("cp.async.cg.shared.global [%0], [%1], 16;" \
        :: "r"((uint32_t)(smem_u32)), "l"(gptr) : "memory")
#define CP_COMMIT() asm volatile("cp.async.commit_group;" ::: "memory")
#define CP_WAIT(n)  asm volatile("cp.async.wait_group %0;" :: "n"(n) : "memory")
// SW128 descriptor: layout=2, version=1(Blackwell), SBO=64, LBO=1
#define SMEM_DESC_BASE_SW128 \
    ((uint64_t(2) << 61) | (uint64_t(1) << 46) | (uint64_t(64) << 32) | (uint64_t(1) << 16))
#define MAKE_SMEM_DESC(addr) (SMEM_DESC_BASE_SW128 | ((uint64_t)((addr) >> 4) & 0x3FFF))
#define SW128(off) ((off) ^ (((off) >> 3) & 0x70))

#if HAS_TCGEN05
__device__ __forceinline__ void mma_f16_ss(uint32_t d_tmem, uint64_t a_desc,
                                           uint64_t b_desc, uint32_t idesc,
                                           bool accum) {
    uint32_t en = accum ? 1u : 0u;
    asm volatile(
        "{\n\t.reg .pred p;\n\tsetp.ne.u32 p, %5, 0;\n\t"
        "tcgen05.mma.cta_group::1.kind::f16 [%0], %1, %2, %3, {%4, %4, %4, %4}, p;\n\t}"
        :: "r"(d_tmem), "l"(a_desc), "l"(b_desc), "r"(idesc), "r"(0u), "r"(en)
        : "memory");
}
#endif

// idesc: dtype F32, atype/btype BF16, M=128; N=128 / 256
#define SIM_IDESC  ((1u << 4) | (1u << 7) | (1u << 10) | ((128u / 8u) << 17) | ((128u / 16u) << 24))
#define GEMM_IDESC ((1u << 4) | (1u << 7) | (1u << 10) | ((256u / 8u) << 17) | ((128u / 16u) << 24))

#if HAS_TCGEN05
// 16 chained K=16 MMAs covering K=256 on 128x256-bf16 SW128 tiles (atom grid
// 16 atom-rows x 4 atom-cols). Called by warp 0 only.
__device__ __forceinline__ void issue_tile_mma(uint32_t d_tmem, uint32_t a_smem,
                                               uint32_t b_smem, uint32_t mbar) {
    uint64_t a_base = MAKE_SMEM_DESC(a_smem);
    uint64_t b_base = MAKE_SMEM_DESC(b_smem);
    if (elect_one_pred()) {
        #pragma unroll
        for (int s = 0; s < 16; s++) {
            uint64_t off = (uint64_t)((s >> 2) * 1024 + (s & 3) * 2);
            mma_f16_ss(d_tmem, a_base + off, b_base + off, SIM_IDESC, s > 0);
        }
        TCGEN05_COMMIT(mbar);
    }
}
#endif

// ---------------------------------------------------------------------------
// K0: Wt[256,2048] bf16 = transpose(W[2048,256] fp32). 64x64 tiles.
// ---------------------------------------------------------------------------
__global__ void __launch_bounds__(256) k_prep(const float* __restrict__ W,
                                              __nv_bfloat16* __restrict__ Wt)
{
    __shared__ float S[64][68];
    const int k0 = blockIdx.x * 64, n0 = blockIdx.y * 64;
    const int tid = threadIdx.x;

    #pragma unroll
    for (int i = 0; i < 4; i++) {
        int t = tid + i * 256;
        int r = t >> 4, c4 = t & 15;
        float4 v = *(const float4*)&W[(size_t)(k0 + r) * PD + n0 + c4 * 4];
        S[r][c4 * 4 + 0] = v.x; S[r][c4 * 4 + 1] = v.y;
        S[r][c4 * 4 + 2] = v.z; S[r][c4 * 4 + 3] = v.w;
    }
    __syncthreads();
    #pragma unroll
    for (int i = 0; i < 2; i++) {
        int u = tid + i * 256;
        int n = u >> 3, ku = u & 7;
        __nv_bfloat162 h[4];
        #pragma unroll
        for (int m = 0; m < 4; m++)
            h[m] = __floats2bfloat162_rn(S[ku * 8 + 2 * m][n], S[ku * 8 + 2 * m + 1][n]);
        *(uint4*)&Wt[(size_t)(n0 + n) * DIM + k0 + ku * 8] = *(uint4*)h;
    }
}

// ---------------------------------------------------------------------------
// K1: tcgen05 GEMM1 + bias + fused L2-normalize -> bf16 only.
// ---------------------------------------------------------------------------
__global__ void __launch_bounds__(256, 1) k_gemm1_tc(
    const float* __restrict__ X, const __nv_bfloat16* __restrict__ Wt,
    const float* __restrict__ b, __nv_bfloat16* __restrict__ Nh)
{
    extern __shared__ __align__(16) char smem[];
    __shared__ float s_red[128][2];
    __shared__ float s_bias[256];

    const int tid = threadIdx.x;
    const int row0 = blockIdx.x * 128;
    s_bias[tid] = b[tid];

#if HAS_TCGEN05
    const uint32_t smem_base = smem_to_u32(smem);
    const uint32_t aoff = ((smem_base + 1024 + 1023) & ~1023u) - smem_base;
    const uint32_t A_OFF = aoff;              // 64 KB
    const uint32_t B_OFF = aoff + 65536;      // 128 KB
    const uint32_t TPTR = 0, MBAR = 16;

    if (tid < 32) {
        TCGEN05_ALLOC(smem_base + TPTR, 256);
        TCGEN05_RELINQUISH();
    }
    if (tid == 0) MBARRIER_INIT(smem_base + MBAR, 1);
    __syncthreads();
    uint32_t tmem;
    asm volatile("ld.shared.b32 %0, [%1];" : "=r"(tmem) : "r"(smem_base + TPTR));

    for (int c = 0; c < 8; c++) {
        const int k0 = c * 256;
        #pragma unroll
        for (int i = 0; i < 16; i++) {
            int u = tid + i * 256;
            int r = u >> 5, q = u & 31;
            float4 v0 = *(const float4*)&X[(size_t)(row0 + r) * DIM + k0 + q * 8];
            float4 v1 = *(const float4*)&X[(size_t)(row0 + r) * DIM + k0 + q * 8 + 4];
            __nv_bfloat162 h[4];
            h[0] = __floats2bfloat162_rn(v0.x, v0.y);
            h[1] = __floats2bfloat162_rn(v0.z, v0.w);
            h[2] = __floats2bfloat162_rn(v1.x, v1.y);
            h[3] = __floats2bfloat162_rn(v1.z, v1.w);
            uint32_t byte_off = (uint32_t)((r >> 3) + ((q >> 3) << 4)) * 1024u
                              + (uint32_t)(r & 7) * 128u + (uint32_t)(q & 7) * 16u;
            *(uint4*)(smem + A_OFF + SW128(byte_off)) = *(uint4*)h;
        }
        #pragma unroll
        for (int i = 0; i < 32; i++) {
            int u = tid + i * 256;
            int r = u >> 5, q = u & 31;
            uint4 v = *(const uint4*)&Wt[(size_t)r * DIM + k0 + q * 8];
            uint32_t byte_off = (uint32_t)((r >> 3) + ((q >> 3) << 5)) * 1024u
                              + (uint32_t)(r & 7) * 128u + (uint32_t)(q & 7) * 16u;
            *(uint4*)(smem + B_OFF + SW128(byte_off)) = v;
        }
        __syncthreads();
        FENCE_PROXY_ASYNC();

        if (tid < 32) {
            uint64_t a_base = MAKE_SMEM_DESC(smem_base + A_OFF);
            uint64_t b_base = MAKE_SMEM_DESC(smem_base + B_OFF);
            if (elect_one_pred()) {
                #pragma unroll
                for (int s = 0; s < 16; s++) {
                    uint64_t offA = (uint64_t)((s >> 2) * 1024 + (s & 3) * 2);
                    uint64_t offB = (uint64_t)((s >> 2) * 2048 + (s & 3) * 2);
                    mma_f16_ss(tmem, a_base + offA, b_base + offB, GEMM_IDESC,
                               (c > 0) || (s > 0));
                }
                TCGEN05_COMMIT(smem_base + MBAR);
            }
        }
        MBARRIER_WAIT_PARITY(smem_base + MBAR, c & 1);
        __syncthreads();
    }
    TCGEN05_FENCE_AFTER();

    const int w = tid >> 5, lane = tid & 31;
    const int row = (w & 3) * 32 + lane;
    const int half = w >> 2;
    const uint32_t tbase = tmem + half * 128;

    float sumsq = 0.f;
    #pragma unroll
    for (int c4 = 0; c4 < 4; c4++) {
        uint32_t r[32];
        TCGEN05_LD_32X32B_X32(r, tbase + c4 * 32);
        TCGEN05_WAIT_LD();
        #pragma unroll
        for (int j = 0; j < 32; j++) {
            float v = __uint_as_float(r[j]) + s_bias[half * 128 + c4 * 32 + j];
            sumsq += v * v;
        }
    }
    s_red[row][half] = sumsq;
    __syncthreads();
    float inv = 1.0f / fmaxf(sqrtf(s_red[row][0] + s_red[row][1]), 1e-12f);

    const size_t gbase = (size_t)(row0 + row) * PD + half * 128;
    #pragma unroll
    for (int c4 = 0; c4 < 4; c4++) {
        uint32_t r[32];
        TCGEN05_LD_32X32B_X32(r, tbase + c4 * 32);
        TCGEN05_WAIT_LD();
        float v[32];
        #pragma unroll
        for (int j = 0; j < 32; j++)
            v[j] = (__uint_as_float(r[j]) + s_bias[half * 128 + c4 * 32 + j]) * inv;
        __nv_bfloat162 hh[16];
        #pragma unroll
        for (int j2 = 0; j2 < 16; j2++)
            hh[j2] = __floats2bfloat162_rn(v[2 * j2], v[2 * j2 + 1]);
        #pragma unroll
        for (int q = 0; q < 4; q++)
            *(uint4*)&Nh[gbase + c4 * 32 + q * 8] = ((uint4*)hh)[q];
    }
    TCGEN05_FENCE_BEFORE();

    __syncthreads();
    if (tid == 0) MBARRIER_INVAL(smem_base + MBAR);
    __syncthreads();
    if (tid < 32) TCGEN05_DEALLOC(tmem, 256);
#else
    const int row = row0 + tid;
    if (tid < 128) {
        float sumsq = 0.f;
        for (int n = 0; n < PD; n++) {
            float s = 0.f;
            for (int k = 0; k < DIM; k++)
                s += X[(size_t)row * DIM + k] * __bfloat162float(Wt[(size_t)n * DIM + k]);
            s += s_bias[n];
            sumsq += s * s;
        }
        float inv = 1.0f / fmaxf(sqrtf(sumsq), 1e-12f);
        for (int n = 0; n < PD; n++) {
            float s = 0.f;
            for (int k = 0; k < DIM; k++)
                s += X[(size_t)row * DIM + k] * __bfloat162float(Wt[(size_t)n * DIM + k]);
            Nh[(size_t)row * PD + n] = __float2bfloat16((s + s_bias[n]) * inv);
        }
    }
#endif
}

// ---------------------------------------------------------------------------
// K3: pos dots from bf16 normalized (warp per i, uint4 loads)
// ---------------------------------------------------------------------------
__global__ void __launch_bounds__(256) k_pos(const __nv_bfloat16* __restrict__ Nh,
                                             float* __restrict__ pos)
{
    int w = (blockIdx.x * blockDim.x + threadIdx.x) >> 5;
    int lane = threadIdx.x & 31;
    if (w >= HALF) return;
    uint4 va = ((const uint4*)(Nh + (size_t)w * PD))[lane];
    uint4 vc = ((const uint4*)(Nh + (size_t)(w + HALF) * PD))[lane];
    const __nv_bfloat162* ha = (const __nv_bfloat162*)&va;
    const __nv_bfloat162* hc = (const __nv_bfloat162*)&vc;
    float s = 0.f;
    #pragma unroll
    for (int m = 0; m < 4; m++) {
        float2 a2 = __bfloat1622float2(ha[m]);
        float2 c2 = __bfloat1622float2(hc[m]);
        s += a2.x * c2.x + a2.y * c2.y;
    }
    #pragma unroll
    for (int o = 16; o > 0; o >>= 1) s += __shfl_down_sync(0xffffffff, s, o);
    if (lane == 0) pos[w] = s;
}

// ---------------------------------------------------------------------------
// K4: A-resident pipelined sim+exp+rowsum. Grid (64 bi, 2 col-half), 128 thr.
// Each CTA: A tile (rows bi*128, K=256) resident; streams 32 B tiles of its
// half with cp.async double-buffering; TMEM ping-pong (D0/D1) overlaps the
// exp/rowsum epilogue of tile t with the MMA of tile t+1. Row sums accumulate
// in registers over all 32 tiles -> part[half][row]. Deterministic order.
// SMEM: ctrl | A 64K | B0 64K | B1 64K
// ---------------------------------------------------------------------------
__global__ void __launch_bounds__(128, 1) k_sim_rows(
    const __nv_bfloat16* __restrict__ Nh, float* __restrict__ part)
{
    extern __shared__ __align__(16) char smem[];
    const int tid = threadIdx.x;
    const int bi = blockIdx.x, half = blockIdx.y;
    const int ro = bi * 128;
    const int gi = ro + tid;

#if HAS_TCGEN05
    const uint32_t smem_base = smem_to_u32(smem);
    const uint32_t aoff = ((smem_base + 1024 + 1023) & ~1023u) - smem_base;
    const uint32_t A_OFF = aoff;
    const uint32_t B_OFF0 = aoff + 65536;
    const uint32_t B_OFF1 = aoff + 131072;
    const uint32_t TPTR = 0, MBAR0 = 16, MBAR1 = 24;

    if (tid < 32) {
        TCGEN05_ALLOC(smem_base + TPTR, 256);
        TCGEN05_RELINQUISH();
    }
    if (tid == 0) { MBARRIER_INIT(smem_base + MBAR0, 1); MBARRIER_INIT(smem_base + MBAR1, 1); }
    __syncthreads();
    uint32_t tmem;
    asm volatile("ld.shared.b32 %0, [%1];" : "=r"(tmem) : "r"(smem_base + TPTR));
    const uint32_t D0 = tmem, D1 = tmem + 128;

    const __nv_bfloat16* Arows = Nh + (size_t)ro * PD;
    const __nv_bfloat16* Bbase = Nh + (size_t)(half * HALF) * PD;

    // Prologue: A + B0 (group 0), B1 (group 1), all cp.async 16B swizzled.
    #pragma unroll
    for (int it = 0; it < 32; it++) {
        int idx = tid + it * 128;
        int r = idx >> 5, q = idx & 31;
        uint32_t byte_off = (uint32_t)((r >> 3) + ((q >> 3) << 4)) * 1024u
                          + (uint32_t)(r & 7) * 128u + (uint32_t)(q & 7) * 16u;
        uint32_t sw = SW128(byte_off);
        CP_ASYNC16(smem_base + A_OFF + sw, Arows + (size_t)r * PD + q * 8);
        CP_ASYNC16(smem_base + B_OFF0 + sw, Bbase + (size_t)r * PD + q * 8);
    }
    CP_COMMIT();
    #pragma unroll
    for (int it = 0; it < 32; it++) {
        int idx = tid + it * 128;
        int r = idx >> 5, q = idx & 31;
        uint32_t byte_off = (uint32_t)((r >> 3) + ((q >> 3) << 4)) * 1024u
                          + (uint32_t)(r & 7) * 128u + (uint32_t)(q & 7) * 16u;
        CP_ASYNC16(smem_base + B_OFF1 + SW128(byte_off),
                   Bbase + (size_t)(128 + r) * PD + q * 8);
    }
    CP_COMMIT();
    CP_WAIT(1);              // A + B0 complete (B1 may fly)
    __syncthreads();
    FENCE_PROXY_ASYNC();

    if (tid < 32) issue_tile_mma(D0, smem_base + A_OFF, smem_base + B_OFF0,
                                 smem_base + MBAR0);

    int ph0 = 0, ph1 = 0;
    float rowsum = 0.f;

    for (int t = 0; t < 32; t++) {
        const int buf = t & 1;
        const uint32_t mb = smem_base + (buf ? MBAR1 : MBAR0);
        const uint32_t bofs = buf ? B_OFF1 : B_OFF0;

        // 1. wait MMA t (frees B[buf], fills D[buf])
        if (buf) { MBARRIER_WAIT_PARITY(mb, ph1); ph1 ^= 1; }
        else     { MBARRIER_WAIT_PARITY(mb, ph0); ph0 ^= 1; }

        // 2. prefetch B_{t+2} into B[buf]
        if (t + 2 < 32) {
            const __nv_bfloat16* Brows = Bbase + (size_t)(t + 2) * 128 * PD;
            #pragma unroll
            for (int it = 0; it < 32; it++) {
                int idx = tid + it * 128;
                int r = idx >> 5, q = idx & 31;
                uint32_t byte_off = (uint32_t)((r >> 3) + ((q >> 3) << 4)) * 1024u
                                  + (uint32_t)(r & 7) * 128u + (uint32_t)(q & 7) * 16u;
                CP_ASYNC16(smem_base + bofs + SW128(byte_off),
                           Brows + (size_t)r * PD + q * 8);
            }
        }
        CP_COMMIT();
        // 3. ensure B_{t+1} resident (allow newest group in flight)
        CP_WAIT(1);
        __syncthreads();
        FENCE_PROXY_ASYNC();
        TCGEN05_FENCE_AFTER();

        // 4. issue MMA t+1 on the other buffers
        if (t + 1 < 32 && tid < 32)
            issue_tile_mma(buf ? D0 : D1, smem_base + A_OFF,
                           buf ? B_OFF0 + smem_base : B_OFF1 + smem_base,
                           smem_base + (buf ? MBAR0 : MBAR1));

        // 5. epilogue on D[buf]: exp + diag mask + rowsum accumulate
        const int jbase = half * HALF + t * 128;
        const uint32_t dt = buf ? D1 : D0;
        #pragma unroll
        for (int c4 = 0; c4 < 4; c4++) {
            uint32_t r[32];
            TCGEN05_LD_32X32B_X32(r, dt + c4 * 32);
            TCGEN05_WAIT_LD();
            #pragma unroll
            for (int j = 0; j < 32; j++) {
                float e = __expf(10.0f * __uint_as_float(r[j]));
                rowsum += (gi == jbase + c4 * 32 + j) ? 0.0f : e;
            }
        }
        TCGEN05_FENCE_BEFORE();
    }

    part[(size_t)half * NROWS + gi] = rowsum;

    __syncthreads();
    if (tid == 0) { MBARRIER_INVAL(smem_base + MBAR0); MBARRIER_INVAL(smem_base + MBAR1); }
    __syncthreads();
    if (tid < 32) TCGEN05_DEALLOC(tmem, 256);
#else
    // SIMT fallback (compile-only for the portable PTX pass)
    const __nv_bfloat16* arow = Nh + (size_t)gi * PD;
    float rowsum = 0.f;
    for (int j = 0; j < HALF; j++) {
        int gj = half * HALF + j;
        const __nv_bfloat16* brow = Nh + (size_t)gj * PD;
        float s = 0.f;
        for (int k = 0; k < PD; k++)
            s += __bfloat162float(arow[k]) * __bfloat162float(brow[k]);
        rowsum += (gi == gj) ? 0.0f : __expf(10.0f * s);
    }
    part[(size_t)half * NROWS + gi] = rowsum;
#endif
}

// ---------------------------------------------------------------------------
// K6: loss = (sum log(part0+part1) - 20 * sum pos) / 8192
// ---------------------------------------------------------------------------
__global__ void __launch_bounds__(256) k_loss(const float* __restrict__ part,
                                              const float* __restrict__ pos,
                                              float* __restrict__ out)
{
    __shared__ float sh[256];
    float s = 0.f;
    for (int i = threadIdx.x; i < NROWS; i += 256)
        s += logf(part[i] + part[NROWS + i]);
    float p = 0.f;
    for (int i = threadIdx.x; i < HALF; i += 256) p += pos[i];

    sh[threadIdx.x] = s;
    __syncthreads();
    #pragma unroll
    for (int o = 128; o > 0; o >>= 1) {
        if (threadIdx.x < o) sh[threadIdx.x] += sh[threadIdx.x + o];
        __syncthreads();
    }
    float sumlog = sh[0];
    __syncthreads();
    sh[threadIdx.x] = p;
    __syncthreads();
    #pragma unroll
    for (int o = 128; o > 0; o >>= 1) {
        if (threadIdx.x < o) sh[threadIdx.x] += sh[threadIdx.x + o];
        __syncthreads();
    }
    if (threadIdx.x == 0)
        out[0] = (sumlog - 20.0f * sh[0]) / (float)NROWS;
}

// ---------------------------------------------------------------------------
extern "C" void kernel_launch(void* const* d_in, const int* in_sizes, int n_in,
                              void* d_out, int out_size)
{
    const float* X = (const float*)d_in[0];  // [8192, 2048]
    const float* W = (const float*)d_in[1];  // [2048, 256]
    const float* b = (const float*)d_in[2];  // [256]
    float* out = (float*)d_out;

    __nv_bfloat16* nrh;  cudaGetSymbolAddress((void**)&nrh,  g_normh);
    __nv_bfloat16* wt;   cudaGetSymbolAddress((void**)&wt,   g_Wt);
    float* part;         cudaGetSymbolAddress((void**)&part, g_part);
    float* pos;          cudaGetSymbolAddress((void**)&pos,  g_pos);

    const int SIM_SMEM  = 2048 + 3 * 65536;   // 198656 B
    const int GEMM_SMEM = 2048 + 65536 + 131072;
    cudaFuncSetAttribute(k_sim_rows,
                         cudaFuncAttributeMaxDynamicSharedMemorySize, SIM_SMEM);
    cudaFuncSetAttribute(k_gemm1_tc,
                         cudaFuncAttributeMaxDynamicSharedMemorySize, GEMM_SMEM);

    k_prep<<<dim3(32, 4), 256>>>(W, wt);
    k_gemm1_tc<<<64, 256, GEMM_SMEM>>>(X, wt, b, nrh);
    k_pos<<<512, 256>>>(nrh, pos);
    k_sim_rows<<<dim3(64, 2), 128, SIM_SMEM>>>(nrh, part);
    k_loss<<<1, 256>>>(part, pos, out);
}

// round 10
// speedup vs baseline: 8.6356x; 1.2855x over previous
#include <cuda_runtime.h>
#include <cuda_bf16.h>
#include <math.h>
#include <cstdint>

// Problem constants
#define NROWS 8192
#define HALF  4096
#define DIM   2048
#define PD    256
#define NT    64

// Feature gate: tcgen05 exists only in the arch-specific sm_103a/sm_100a SASS
// pass. The portable compute_103 PTX pass gets a SIMT fallback (never run).
#if !defined(__CUDA_ARCH__) || defined(__CUDA_ARCH_FEAT_SM103_ALL) || defined(__CUDA_ARCH_FEAT_SM100_ALL)
#define HAS_TCGEN05 1
#else
#define HAS_TCGEN05 0
#endif

// Scratch (device globals; no allocation allowed)
__device__ __nv_bfloat16 g_normh[NROWS * PD];   // bf16 normalized (4 MB)
__device__ __nv_bfloat16 g_Wt[PD * DIM];        // W^T bf16 [256,2048] (1 MB)
__device__ float         g_part[2 * NROWS];     // per-col-half row sums
__device__ float         g_pos[HALF];

// ---------------------------------------------------------------------------
// PTX helpers
// ---------------------------------------------------------------------------
__device__ __forceinline__ uint32_t smem_to_u32(const void* p) {
    uint32_t a;
    asm("{ .reg .u64 t; cvta.to.shared.u64 t, %1; cvt.u32.u64 %0, t; }"
        : "=r"(a) : "l"(p));
    return a;
}
__device__ __forceinline__ uint32_t elect_one_pred() {
    uint32_t pred;
    asm volatile("{\n\t.reg .pred p;\n\telect.sync _|p, 0xFFFFFFFF;\n\t"
                 "selp.b32 %0, 1, 0, p;\n\t}" : "=r"(pred));
    return pred;
}
#define TCGEN05_ALLOC(smem_addr, nCols) \
    asm volatile("tcgen05.alloc.cta_group::1.sync.aligned.shared::cta.b32 [%0], %1;" \
        :: "r"((uint32_t)(smem_addr)), "r"((uint32_t)(nCols)) : "memory")
#define TCGEN05_DEALLOC(tmem, nCols) \
    asm volatile("tcgen05.dealloc.cta_group::1.sync.aligned.b32 %0, %1;" \
        :: "r"(tmem), "r"((uint32_t)(nCols)))
#define TCGEN05_RELINQUISH() \
    asm volatile("tcgen05.relinquish_alloc_permit.cta_group::1.sync.aligned;")
#define TCGEN05_COMMIT(mbar) \
    asm volatile("tcgen05.commit.cta_group::1.mbarrier::arrive::one.shared::cluster.b64 [%0];" \
        :: "r"((uint32_t)(mbar)) : "memory")
#define TCGEN05_WAIT_LD()  asm volatile("tcgen05.wait::ld.sync.aligned;" ::: "memory")
#define TCGEN05_FENCE_BEFORE() asm volatile("tcgen05.fence::before_thread_sync;" ::: "memory")
#define TCGEN05_FENCE_AFTER()  asm volatile("tcgen05.fence::after_thread_sync;" ::: "memory")
#define FENCE_PROXY_ASYNC() asm volatile("fence.proxy.async.shared::cta;" ::: "memory")
#define MBARRIER_INIT(mbar, cnt) \
    asm volatile("mbarrier.init.shared.b64 [%0], %1;" \
        :: "r"((uint32_t)(mbar)), "r"((uint32_t)(cnt)) : "memory")
#define MBARRIER_INVAL(mbar) \
    asm volatile("mbarrier.inval.shared.b64 [%0];" :: "r"((uint32_t)(mbar)) : "memory")
#define MBARRIER_WAIT_PARITY(mbar, par) do {                                     \
    uint32_t _m = (uint32_t)(mbar), _p = (uint32_t)(par), _d;                    \
    asm volatile("{\n\t.reg .pred p;\n\t"                                        \
        "mbarrier.try_wait.parity.acquire.cta.shared::cta.b64 p, [%1], %2;\n\t"  \
        "selp.b32 %0, 1, 0, p;\n\t}" : "=r"(_d) : "r"(_m), "r"(_p) : "memory");  \
    if (!_d) {                                                                   \
        asm volatile("{\n\t.reg .pred P1;\n\tWL_%=:\n\t"                         \
            "mbarrier.try_wait.parity.acquire.cta.shared::cta.b64 P1, [%0], %1, 0x989680;\n\t" \
            "@P1 bra.uni WD_%=;\n\tbra.uni WL_%=;\n\tWD_%=:\n\t}"                \
            :: "r"(_m), "r"(_p) : "memory");                                     \
    } } while (0)
#define TCGEN05_LD_32X32B_X32(r, tmem) \
    asm volatile("tcgen05.ld.sync.aligned.32x32b.x32.b32 " \
        "{%0, %1, %2, %3, %4, %5, %6, %7, %8, %9, %10, %11, %12, %13, %14, %15, " \
        "%16, %17, %18, %19, %20, %21, %22, %23, %24, %25, %26, %27, %28, %29, %30, %31}, [%32];" \
        : "=r"((r)[0]),  "=r"((r)[1]),  "=r"((r)[2]),  "=r"((r)[3]),  \
          "=r"((r)[4]),  "=r"((r)[5]),  "=r"((r)[6]),  "=r"((r)[7]),  \
          "=r"((r)[8]),  "=r"((r)[9]),  "=r"((r)[10]), "=r"((r)[11]), \
          "=r"((r)[12]), "=r"((r)[13]), "=r"((r)[14]), "=r"((r)[15]), \
          "=r"((r)[16]), "=r"((r)[17]), "=r"((r)[18]), "=r"((r)[19]), \
          "=r"((r)[20]), "=r"((r)[21]), "=r"((r)[22]), "=r"((r)[23]), \
          "=r"((r)[24]), "=r"((r)[25]), "=r"((r)[26]), "=r"((r)[27]), \
          "=r"((r)[28]), "=r"((r)[29]), "=r"((r)[30]), "=r"((r)[31]) \
        : "r"(tmem))
#define CP_ASYNC16(smem_u32, gptr) \
    asm volatile("cp.async.cg.shared.global [%0], [%1], 16;" \
        :: "r"((uint32_t)(smem_u32)), "l"(gptr) : "memory")
#define CP_COMMIT() asm volatile("cp.async.commit_group;" ::: "memory")
#define CP_WAIT(n)  asm volatile("cp.async.wait_group %0;" :: "n"(n) : "memory")
// SW128 descriptor: layout=2, version=1(Blackwell), SBO=64, LBO=1
#define SMEM_DESC_BASE_SW128 \
    ((uint64_t(2) << 61) | (uint64_t(1) << 46) | (uint64_t(64) << 32) | (uint64_t(1) << 16))
#define MAKE_SMEM_DESC(addr) (SMEM_DESC_BASE_SW128 | ((uint64_t)((addr) >> 4) & 0x3FFF))
#define SW128(off) ((off) ^ (((off) >> 3) & 0x70))

#if HAS_TCGEN05
__device__ __forceinline__ void mma_f16_ss(uint32_t d_tmem, uint64_t a_desc,
                                           uint64_t b_desc, uint32_t idesc,
                                           bool accum) {
    uint32_t en = accum ? 1u : 0u;
    asm volatile(
        "{\n\t.reg .pred p;\n\tsetp.ne.u32 p, %5, 0;\n\t"
        "tcgen05.mma.cta_group::1.kind::f16 [%0], %1, %2, %3, {%4, %4, %4, %4}, p;\n\t}"
        :: "r"(d_tmem), "l"(a_desc), "l"(b_desc), "r"(idesc), "r"(0u), "r"(en)
        : "memory");
}
#endif

// idesc: dtype F32, atype/btype BF16, M=128; N=128 / 256
#define SIM_IDESC  ((1u << 4) | (1u << 7) | (1u << 10) | ((128u / 8u) << 17) | ((128u / 16u) << 24))
#define GEMM_IDESC ((1u << 4) | (1u << 7) | (1u << 10) | ((256u / 8u) << 17) | ((128u / 16u) << 24))

#if HAS_TCGEN05
// 16 chained K=16 MMAs, K=256, 128x256-bf16 SW128 tiles (16 atom-rows x 4 cols)
__device__ __forceinline__ void issue_tile_mma(uint32_t d_tmem, uint32_t a_smem,
                                               uint32_t b_smem, uint32_t mbar) {
    uint64_t a_base = MAKE_SMEM_DESC(a_smem);
    uint64_t b_base = MAKE_SMEM_DESC(b_smem);
    if (elect_one_pred()) {
        #pragma unroll
        for (int s = 0; s < 16; s++) {
            uint64_t off = (uint64_t)((s >> 2) * 1024 + (s & 3) * 2);
            mma_f16_ss(d_tmem, a_base + off, b_base + off, SIM_IDESC, s > 0);
        }
        TCGEN05_COMMIT(mbar);
    }
}
// 8 chained K=16 MMAs, K=128: A tile 128x128 (16 atom-rows x 2 cols),
// B tile 256x128 (32 atom-rows x 2 cols), N=256.
__device__ __forceinline__ void g1_issue(uint32_t d_tmem, uint32_t a_smem,
                                         uint32_t b_smem, uint32_t mbar,
                                         bool first_chunk) {
    uint64_t a_base = MAKE_SMEM_DESC(a_smem);
    uint64_t b_base = MAKE_SMEM_DESC(b_smem);
    if (elect_one_pred()) {
        #pragma unroll
        for (int s = 0; s < 8; s++) {
            uint64_t offA = (uint64_t)((s >> 2) * 1024 + (s & 3) * 2);
            uint64_t offB = (uint64_t)((s >> 2) * 2048 + (s & 3) * 2);
            mma_f16_ss(d_tmem, a_base + offA, b_base + offB, GEMM_IDESC,
                       !(first_chunk && s == 0));
        }
        TCGEN05_COMMIT(mbar);
    }
}
// A chunk loader: X[row0..row0+127][k0..k0+127] fp32 -> bf16 SW128 (32 KB)
__device__ __forceinline__ void g1_load_A(const float* __restrict__ X, int row0,
                                          int k0, char* smem, uint32_t A_OFF,
                                          int tid) {
    #pragma unroll
    for (int i = 0; i < 8; i++) {
        int u = tid + i * 256;             // 0..2047 16B units
        int r = u >> 4, q = u & 15;
        const float* src = X + (size_t)(row0 + r) * DIM + k0 + q * 8;
        float4 v0 = *(const float4*)src;
        float4 v1 = *(const float4*)(src + 4);
        __nv_bfloat162 h[4];
        h[0] = __floats2bfloat162_rn(v0.x, v0.y);
        h[1] = __floats2bfloat162_rn(v0.z, v0.w);
        h[2] = __floats2bfloat162_rn(v1.x, v1.y);
        h[3] = __floats2bfloat162_rn(v1.z, v1.w);
        uint32_t byte_off = (uint32_t)((r >> 3) + ((q >> 3) << 4)) * 1024u
                          + (uint32_t)(r & 7) * 128u + (uint32_t)(q & 7) * 16u;
        *(uint4*)(smem + A_OFF + SW128(byte_off)) = *(uint4*)h;
    }
}
// B chunk loader: Wt[0..255][k0..k0+127] bf16 via cp.async (64 KB)
__device__ __forceinline__ void g1_load_B(const __nv_bfloat16* __restrict__ Wt,
                                          int k0, uint32_t smem_base,
                                          uint32_t B_OFF, int tid) {
    #pragma unroll
    for (int i = 0; i < 16; i++) {
        int u = tid + i * 256;             // 0..4095 16B units
        int r = u >> 4, q = u & 15;
        uint32_t byte_off = (uint32_t)((r >> 3) + ((q >> 3) << 5)) * 1024u
                          + (uint32_t)(r & 7) * 128u + (uint32_t)(q & 7) * 16u;
        CP_ASYNC16(smem_base + B_OFF + SW128(byte_off),
                   Wt + (size_t)r * DIM + k0 + q * 8);
    }
}
#endif

// ---------------------------------------------------------------------------
// K0: Wt[256,2048] bf16 = transpose(W[2048,256] fp32). 64x64 tiles.
// ---------------------------------------------------------------------------
__global__ void __launch_bounds__(256) k_prep(const float* __restrict__ W,
                                              __nv_bfloat16* __restrict__ Wt)
{
    __shared__ float S[64][68];
    const int k0 = blockIdx.x * 64, n0 = blockIdx.y * 64;
    const int tid = threadIdx.x;

    #pragma unroll
    for (int i = 0; i < 4; i++) {
        int t = tid + i * 256;
        int r = t >> 4, c4 = t & 15;
        float4 v = *(const float4*)&W[(size_t)(k0 + r) * PD + n0 + c4 * 4];
        S[r][c4 * 4 + 0] = v.x; S[r][c4 * 4 + 1] = v.y;
        S[r][c4 * 4 + 2] = v.z; S[r][c4 * 4 + 3] = v.w;
    }
    __syncthreads();
    #pragma unroll
    for (int i = 0; i < 2; i++) {
        int u = tid + i * 256;
        int n = u >> 3, ku = u & 7;
        __nv_bfloat162 h[4];
        #pragma unroll
        for (int m = 0; m < 4; m++)
            h[m] = __floats2bfloat162_rn(S[ku * 8 + 2 * m][n], S[ku * 8 + 2 * m + 1][n]);
        *(uint4*)&Wt[(size_t)(n0 + n) * DIM + k0 + ku * 8] = *(uint4*)h;
    }
}

// ---------------------------------------------------------------------------
// K1: tcgen05 GEMM1 + bias + fused L2-normalize -> bf16.
// K=128 chunks, DOUBLE-BUFFERED (A: 2x32K LDG+cvt; B: 2x64K cp.async).
// MMA chunk c overlaps loads for chunk c+1; mbar waits gate buffer reuse only
// (tcgen05 queue is in-order, so chained accumulation needs no waits).
// ---------------------------------------------------------------------------
__global__ void __launch_bounds__(256, 1) k_gemm1_tc(
    const float* __restrict__ X, const __nv_bfloat16* __restrict__ Wt,
    const float* __restrict__ b, __nv_bfloat16* __restrict__ Nh)
{
    extern __shared__ __align__(16) char smem[];
    __shared__ float s_red[128][2];
    __shared__ float s_bias[256];

    const int tid = threadIdx.x;
    const int row0 = blockIdx.x * 128;
    s_bias[tid] = b[tid];

#if HAS_TCGEN05
    const uint32_t smem_base = smem_to_u32(smem);
    const uint32_t aoff = ((smem_base + 1024 + 1023) & ~1023u) - smem_base;
    const uint32_t A_OFF0 = aoff;               // 32 KB
    const uint32_t A_OFF1 = aoff + 32768;       // 32 KB
    const uint32_t B_OFF0 = aoff + 65536;       // 64 KB
    const uint32_t B_OFF1 = aoff + 131072;      // 64 KB
    const uint32_t TPTR = 0, MB0 = 16, MB1 = 24;

    if (tid < 32) {
        TCGEN05_ALLOC(smem_base + TPTR, 256);
        TCGEN05_RELINQUISH();
    }
    if (tid == 0) { MBARRIER_INIT(smem_base + MB0, 1); MBARRIER_INIT(smem_base + MB1, 1); }
    __syncthreads();
    uint32_t tmem;
    asm volatile("ld.shared.b32 %0, [%1];" : "=r"(tmem) : "r"(smem_base + TPTR));

    // prologue: chunk 0
    g1_load_B(Wt, 0, smem_base, B_OFF0, tid);
    CP_COMMIT();
    g1_load_A(X, row0, 0, smem, A_OFF0, tid);
    CP_WAIT(0);
    __syncthreads();
    FENCE_PROXY_ASYNC();

    int ph0 = 0, ph1 = 0;
    for (int c = 0; c < 16; c++) {
        const int buf = c & 1;
        if (tid < 32)
            g1_issue(tmem, smem_base + (buf ? A_OFF1 : A_OFF0),
                     smem_base + (buf ? B_OFF1 : B_OFF0),
                     smem_base + (buf ? MB1 : MB0), c == 0);
        if (c + 1 < 16) {
            if (c >= 1) {   // free the other buffer: wait MMA c-1
                if (buf) { MBARRIER_WAIT_PARITY(smem_base + MB0, ph0); ph0 ^= 1; }
                else     { MBARRIER_WAIT_PARITY(smem_base + MB1, ph1); ph1 ^= 1; }
            }
            g1_load_B(Wt, (c + 1) * 128, smem_base, buf ? B_OFF0 : B_OFF1, tid);
            CP_COMMIT();
            g1_load_A(X, row0, (c + 1) * 128, smem, buf ? A_OFF0 : A_OFF1, tid);
            CP_WAIT(0);
            __syncthreads();
            FENCE_PROXY_ASYNC();
        }
    }
    MBARRIER_WAIT_PARITY(smem_base + MB1, ph1);   // MMA 15 (odd -> MB1)
    TCGEN05_FENCE_AFTER();

    // Epilogue: warp w -> rows (w&3)*32+lane, col half w>>2 (128 cols each)
    const int w = tid >> 5, lane = tid & 31;
    const int row = (w & 3) * 32 + lane;
    const int half = w >> 2;
    const uint32_t tbase = tmem + half * 128;

    float sumsq = 0.f;
    #pragma unroll
    for (int c4 = 0; c4 < 4; c4++) {
        uint32_t r[32];
        TCGEN05_LD_32X32B_X32(r, tbase + c4 * 32);
        TCGEN05_WAIT_LD();
        #pragma unroll
        for (int j = 0; j < 32; j++) {
            float v = __uint_as_float(r[j]) + s_bias[half * 128 + c4 * 32 + j];
            sumsq += v * v;
        }
    }
    s_red[row][half] = sumsq;
    __syncthreads();
    float inv = 1.0f / fmaxf(sqrtf(s_red[row][0] + s_red[row][1]), 1e-12f);

    const size_t gbase = (size_t)(row0 + row) * PD + half * 128;
    #pragma unroll
    for (int c4 = 0; c4 < 4; c4++) {
        uint32_t r[32];
        TCGEN05_LD_32X32B_X32(r, tbase + c4 * 32);
        TCGEN05_WAIT_LD();
        float v[32];
        #pragma unroll
        for (int j = 0; j < 32; j++)
            v[j] = (__uint_as_float(r[j]) + s_bias[half * 128 + c4 * 32 + j]) * inv;
        __nv_bfloat162 hh[16];
        #pragma unroll
        for (int j2 = 0; j2 < 16; j2++)
            hh[j2] = __floats2bfloat162_rn(v[2 * j2], v[2 * j2 + 1]);
        #pragma unroll
        for (int q = 0; q < 4; q++)
            *(uint4*)&Nh[gbase + c4 * 32 + q * 8] = ((uint4*)hh)[q];
    }
    TCGEN05_FENCE_BEFORE();

    __syncthreads();
    if (tid == 0) { MBARRIER_INVAL(smem_base + MB0); MBARRIER_INVAL(smem_base + MB1); }
    __syncthreads();
    if (tid < 32) TCGEN05_DEALLOC(tmem, 256);
#else
    const int row = row0 + (tid & 127);
    if (tid < 128) {
        float sumsq = 0.f;
        for (int n = 0; n < PD; n++) {
            float s = 0.f;
            for (int k = 0; k < DIM; k++)
                s += X[(size_t)row * DIM + k] * __bfloat162float(Wt[(size_t)n * DIM + k]);
            s += s_bias[n];
            sumsq += s * s;
        }
        float inv = 1.0f / fmaxf(sqrtf(sumsq), 1e-12f);
        for (int n = 0; n < PD; n++) {
            float s = 0.f;
            for (int k = 0; k < DIM; k++)
                s += X[(size_t)row * DIM + k] * __bfloat162float(Wt[(size_t)n * DIM + k]);
            Nh[(size_t)row * PD + n] = __float2bfloat16((s + s_bias[n]) * inv);
        }
    }
#endif
}

// ---------------------------------------------------------------------------
// K3: pos dots from bf16 normalized (warp per i)
// ---------------------------------------------------------------------------
__global__ void __launch_bounds__(256) k_pos(const __nv_bfloat16* __restrict__ Nh,
                                             float* __restrict__ pos)
{
    int w = (blockIdx.x * blockDim.x + threadIdx.x) >> 5;
    int lane = threadIdx.x & 31;
    if (w >= HALF) return;
    uint4 va = ((const uint4*)(Nh + (size_t)w * PD))[lane];
    uint4 vc = ((const uint4*)(Nh + (size_t)(w + HALF) * PD))[lane];
    const __nv_bfloat162* ha = (const __nv_bfloat162*)&va;
    const __nv_bfloat162* hc = (const __nv_bfloat162*)&vc;
    float s = 0.f;
    #pragma unroll
    for (int m = 0; m < 4; m++) {
        float2 a2 = __bfloat1622float2(ha[m]);
        float2 c2 = __bfloat1622float2(hc[m]);
        s += a2.x * c2.x + a2.y * c2.y;
    }
    #pragma unroll
    for (int o = 16; o > 0; o >>= 1) s += __shfl_down_sync(0xffffffff, s, o);
    if (lane == 0) pos[w] = s;
}

// ---------------------------------------------------------------------------
// K4: A-resident pipelined sim+exp+rowsum. Grid (64 bi, 2 bhalf), 256 thr.
// 8-warp epilogue split by column half; hoisted swizzle addressing; cp.async
// double-buffered B; TMEM ping-pong D0/D1 overlaps epilogue t with MMA t+1.
// ---------------------------------------------------------------------------
__global__ void __launch_bounds__(256, 1) k_sim_rows(
    const __nv_bfloat16* __restrict__ Nh, float* __restrict__ part)
{
    extern __shared__ __align__(16) char smem[];
    __shared__ float s_red[128][2];
    const int tid = threadIdx.x;
    const int bi = blockIdx.x, bhalf = blockIdx.y;
    const int ro = bi * 128;

#if HAS_TCGEN05
    const uint32_t smem_base = smem_to_u32(smem);
    const uint32_t aoff = ((smem_base + 1024 + 1023) & ~1023u) - smem_base;
    const uint32_t A_OFF = aoff;
    const uint32_t B_OFF0 = aoff + 65536;
    const uint32_t B_OFF1 = aoff + 131072;
    const uint32_t TPTR = 0, MBAR0 = 16, MBAR1 = 24;

    if (tid < 32) {
        TCGEN05_ALLOC(smem_base + TPTR, 256);
        TCGEN05_RELINQUISH();
    }
    if (tid == 0) { MBARRIER_INIT(smem_base + MBAR0, 1); MBARRIER_INIT(smem_base + MBAR1, 1); }
    __syncthreads();
    uint32_t tmem;
    asm volatile("ld.shared.b32 %0, [%1];" : "=r"(tmem) : "r"(smem_base + TPTR));
    const uint32_t D0 = tmem, D1 = tmem + 128;

    const __nv_bfloat16* Arows = Nh + (size_t)ro * PD;
    const __nv_bfloat16* Bbase = Nh + (size_t)(bhalf * HALF) * PD;

    // Hoisted addressing: 16 16B-units per thread, constant across tiles.
    uint32_t sw_arr[16], goff[16];
    #pragma unroll
    for (int it = 0; it < 16; it++) {
        int idx = tid + it * 256;          // 0..4095
        int r = idx >> 5, q = idx & 31;
        uint32_t byte_off = (uint32_t)((r >> 3) + ((q >> 3) << 4)) * 1024u
                          + (uint32_t)(r & 7) * 128u + (uint32_t)(q & 7) * 16u;
        sw_arr[it] = SW128(byte_off);
        goff[it] = (uint32_t)(r * PD + q * 8);
    }

    // Prologue: A + B0 (group 0), B1 (group 1)
    #pragma unroll
    for (int it = 0; it < 16; it++) {
        CP_ASYNC16(smem_base + A_OFF + sw_arr[it], Arows + goff[it]);
        CP_ASYNC16(smem_base + B_OFF0 + sw_arr[it], Bbase + goff[it]);
    }
    CP_COMMIT();
    #pragma unroll
    for (int it = 0; it < 16; it++)
        CP_ASYNC16(smem_base + B_OFF1 + sw_arr[it], Bbase + 128 * PD + goff[it]);
    CP_COMMIT();
    CP_WAIT(1);
    __syncthreads();
    FENCE_PROXY_ASYNC();

    if (tid < 32) issue_tile_mma(D0, smem_base + A_OFF, smem_base + B_OFF0,
                                 smem_base + MBAR0);

    // Epilogue mapping: warp w -> rows (w&3)*32+lane, col half w>>2 (64 cols)
    const int w = tid >> 5, lane = tid & 31;
    const int row = (w & 3) * 32 + lane;
    const int chalf = w >> 2;
    const int gi = ro + row;

    int ph0 = 0, ph1 = 0;
    float rowsum = 0.f;

    for (int t = 0; t < 32; t++) {
        const int buf = t & 1;
        const uint32_t mb = smem_base + (buf ? MBAR1 : MBAR0);
        const uint32_t bofs = buf ? B_OFF1 : B_OFF0;

        // 1. wait MMA t (frees B[buf], fills D[buf])
        if (buf) { MBARRIER_WAIT_PARITY(mb, ph1); ph1 ^= 1; }
        else     { MBARRIER_WAIT_PARITY(mb, ph0); ph0 ^= 1; }

        // 2. prefetch B_{t+2} into B[buf]
        if (t + 2 < 32) {
            const __nv_bfloat16* Brows = Bbase + (size_t)(t + 2) * 128 * PD;
            #pragma unroll
            for (int it = 0; it < 16; it++)
                CP_ASYNC16(smem_base + bofs + sw_arr[it], Brows + goff[it]);
        }
        CP_COMMIT();
        // 3. ensure B_{t+1} resident (newest group may fly)
        CP_WAIT(1);
        __syncthreads();
        FENCE_PROXY_ASYNC();
        TCGEN05_FENCE_AFTER();

        // 4. issue MMA t+1 on the other buffers
        if (t + 1 < 32 && tid < 32)
            issue_tile_mma(buf ? D0 : D1, smem_base + A_OFF,
                           smem_base + (buf ? B_OFF0 : B_OFF1),
                           smem_base + (buf ? MBAR0 : MBAR1));

        // 5. epilogue on D[buf]: exp + diag mask + rowsum (64 cols/thread)
        const int jbase = bhalf * HALF + t * 128 + chalf * 64;
        const uint32_t dt = (buf ? D1 : D0) + chalf * 64;
        #pragma unroll
        for (int c4 = 0; c4 < 2; c4++) {
            uint32_t r[32];
            TCGEN05_LD_32X32B_X32(r, dt + c4 * 32);
            TCGEN05_WAIT_LD();
            #pragma unroll
            for (int j = 0; j < 32; j++) {
                float e = __expf(10.0f * __uint_as_float(r[j]));
                rowsum += (gi == jbase + c4 * 32 + j) ? 0.0f : e;
            }
        }
        TCGEN05_FENCE_BEFORE();
    }

    s_red[row][chalf] = rowsum;
    __syncthreads();
    if (tid < 128)
        part[(size_t)bhalf * NROWS + ro + tid] = s_red[tid][0] + s_red[tid][1];

    __syncthreads();
    if (tid == 0) { MBARRIER_INVAL(smem_base + MBAR0); MBARRIER_INVAL(smem_base + MBAR1); }
    __syncthreads();
    if (tid < 32) TCGEN05_DEALLOC(tmem, 256);
#else
    // SIMT fallback (compile-only for the portable PTX pass)
    if (tid < 128) {
        const int gi = ro + tid;
        const __nv_bfloat16* arow = Nh + (size_t)gi * PD;
        float rowsum = 0.f;
        for (int j = 0; j < HALF; j++) {
            int gj = bhalf * HALF + j;
            const __nv_bfloat16* brow = Nh + (size_t)gj * PD;
            float s = 0.f;
            for (int k = 0; k < PD; k++)
                s += __bfloat162float(arow[k]) * __bfloat162float(brow[k]);
            rowsum += (gi == gj) ? 0.0f : __expf(10.0f * s);
        }
        part[(size_t)bhalf * NROWS + gi] = rowsum;
    }
#endif
}

// ---------------------------------------------------------------------------
// K6: loss = (sum log(part0+part1) - 20 * sum pos) / 8192
// ---------------------------------------------------------------------------
__global__ void __launch_bounds__(256) k_loss(const float* __restrict__ part,
                                              const float* __restrict__ pos,
                                              float* __restrict__ out)
{
    __shared__ float sh[256];
    float s = 0.f;
    for (int i = threadIdx.x; i < NROWS; i += 256)
        s += logf(part[i] + part[NROWS + i]);
    float p = 0.f;
    for (int i = threadIdx.x; i < HALF; i += 256) p += pos[i];

    sh[threadIdx.x] = s;
    __syncthreads();
    #pragma unroll
    for (int o = 128; o > 0; o >>= 1) {
        if (threadIdx.x < o) sh[threadIdx.x] += sh[threadIdx.x + o];
        __syncthreads();
    }
    float sumlog = sh[0];
    __syncthreads();
    sh[threadIdx.x] = p;
    __syncthreads();
    #pragma unroll
    for (int o = 128; o > 0; o >>= 1) {
        if (threadIdx.x < o) sh[threadIdx.x] += sh[threadIdx.x + o];
        __syncthreads();
    }
    if (threadIdx.x == 0)
        out[0] = (sumlog - 20.0f * sh[0]) / (float)NROWS;
}

// ---------------------------------------------------------------------------
extern "C" void kernel_launch(void* const* d_in, const int* in_sizes, int n_in,
                              void* d_out, int out_size)
{
    const float* X = (const float*)d_in[0];  // [8192, 2048]
    const float* W = (const float*)d_in[1];  // [2048, 256]
    const float* b = (const float*)d_in[2];  // [256]
    float* out = (float*)d_out;

    __nv_bfloat16* nrh;  cudaGetSymbolAddress((void**)&nrh,  g_normh);
    __nv_bfloat16* wt;   cudaGetSymbolAddress((void**)&wt,   g_Wt);
    float* part;         cudaGetSymbolAddress((void**)&part, g_part);
    float* pos;          cudaGetSymbolAddress((void**)&pos,  g_pos);

    const int SIM_SMEM  = 2048 + 3 * 65536;             // 198656 B
    const int GEMM_SMEM = 2048 + 2 * 32768 + 2 * 65536; // 198656 B
    cudaFuncSetAttribute(k_sim_rows,
                         cudaFuncAttributeMaxDynamicSharedMemorySize, SIM_SMEM);
    cudaFuncSetAttribute(k_gemm1_tc,
                         cudaFuncAttributeMaxDynamicSharedMemorySize, GEMM_SMEM);

    k_prep<<<dim3(32, 4), 256>>>(W, wt);
    k_gemm1_tc<<<64, 256, GEMM_SMEM>>>(X, wt, b, nrh);
    k_pos<<<512, 256>>>(nrh, pos);
    k_sim_rows<<<dim3(64, 2), 256, SIM_SMEM>>>(nrh, part);
    k_loss<<<1, 256>>>(part, pos, out);
}

// round 11
// speedup vs baseline: 9.1592x; 1.0606x over previous
#include <cuda_runtime.h>
#include <cuda_bf16.h>
#include <math.h>
#include <cstdint>

// Problem constants
#define NROWS 8192
#define HALF  4096
#define DIM   2048
#define PD    256
#define NT    64

// Feature gate: tcgen05 exists only in the arch-specific sm_103a/sm_100a SASS
// pass. The portable compute_103 PTX pass gets a SIMT fallback (never run).
#if !defined(__CUDA_ARCH__) || defined(__CUDA_ARCH_FEAT_SM103_ALL) || defined(__CUDA_ARCH_FEAT_SM100_ALL)
#define HAS_TCGEN05 1
#else
#define HAS_TCGEN05 0
#endif

// Scratch (device globals; no allocation allowed)
__device__ __nv_bfloat16 g_normh[NROWS * PD];   // bf16 normalized (4 MB)
__device__ __nv_bfloat16 g_Wt[PD * DIM];        // W^T bf16 [256,2048] (1 MB)
__device__ float         g_part[2 * NROWS];     // per-col-half row sums
__device__ float         g_pos[HALF];

// ---------------------------------------------------------------------------
// PTX helpers
// ---------------------------------------------------------------------------
__device__ __forceinline__ uint32_t smem_to_u32(const void* p) {
    uint32_t a;
    asm("{ .reg .u64 t; cvta.to.shared.u64 t, %1; cvt.u32.u64 %0, t; }"
        : "=r"(a) : "l"(p));
    return a;
}
__device__ __forceinline__ uint32_t elect_one_pred() {
    uint32_t pred;
    asm volatile("{\n\t.reg .pred p;\n\telect.sync _|p, 0xFFFFFFFF;\n\t"
                 "selp.b32 %0, 1, 0, p;\n\t}" : "=r"(pred));
    return pred;
}
#define TCGEN05_ALLOC(smem_addr, nCols) \
    asm volatile("tcgen05.alloc.cta_group::1.sync.aligned.shared::cta.b32 [%0], %1;" \
        :: "r"((uint32_t)(smem_addr)), "r"((uint32_t)(nCols)) : "memory")
#define TCGEN05_DEALLOC(tmem, nCols) \
    asm volatile("tcgen05.dealloc.cta_group::1.sync.aligned.b32 %0, %1;" \
        :: "r"(tmem), "r"((uint32_t)(nCols)))
#define TCGEN05_RELINQUISH() \
    asm volatile("tcgen05.relinquish_alloc_permit.cta_group::1.sync.aligned;")
#define TCGEN05_COMMIT(mbar) \
    asm volatile("tcgen05.commit.cta_group::1.mbarrier::arrive::one.shared::cluster.b64 [%0];" \
        :: "r"((uint32_t)(mbar)) : "memory")
#define TCGEN05_WAIT_LD()  asm volatile("tcgen05.wait::ld.sync.aligned;" ::: "memory")
#define TCGEN05_FENCE_BEFORE() asm volatile("tcgen05.fence::before_thread_sync;" ::: "memory")
#define TCGEN05_FENCE_AFTER()  asm volatile("tcgen05.fence::after_thread_sync;" ::: "memory")
#define FENCE_PROXY_ASYNC() asm volatile("fence.proxy.async.shared::cta;" ::: "memory")
#define MBARRIER_INIT(mbar, cnt) \
    asm volatile("mbarrier.init.shared.b64 [%0], %1;" \
        :: "r"((uint32_t)(mbar)), "r"((uint32_t)(cnt)) : "memory")
#define MBARRIER_INVAL(mbar) \
    asm volatile("mbarrier.inval.shared.b64 [%0];" :: "r"((uint32_t)(mbar)) : "memory")
#define MBARRIER_WAIT_PARITY(mbar, par) do {                                     \
    uint32_t _m = (uint32_t)(mbar), _p = (uint32_t)(par), _d;                    \
    asm volatile("{\n\t.reg .pred p;\n\t"                                        \
        "mbarrier.try_wait.parity.acquire.cta.shared::cta.b64 p, [%1], %2;\n\t"  \
        "selp.b32 %0, 1, 0, p;\n\t}" : "=r"(_d) : "r"(_m), "r"(_p) : "memory");  \
    if (!_d) {                                                                   \
        asm volatile("{\n\t.reg .pred P1;\n\tWL_%=:\n\t"                         \
            "mbarrier.try_wait.parity.acquire.cta.shared::cta.b64 P1, [%0], %1, 0x989680;\n\t" \
            "@P1 bra.uni WD_%=;\n\tbra.uni WL_%=;\n\tWD_%=:\n\t}"                \
            :: "r"(_m), "r"(_p) : "memory");                                     \
    } } while (0)
#define TCGEN05_LD_32X32B_X32(r, tmem) \
    asm volatile("tcgen05.ld.sync.aligned.32x32b.x32.b32 " \
        "{%0, %1, %2, %3, %4, %5, %6, %7, %8, %9, %10, %11, %12, %13, %14, %15, " \
        "%16, %17, %18, %19, %20, %21, %22, %23, %24, %25, %26, %27, %28, %29, %30, %31}, [%32];" \
        : "=r"((r)[0]),  "=r"((r)[1]),  "=r"((r)[2]),  "=r"((r)[3]),  \
          "=r"((r)[4]),  "=r"((r)[5]),  "=r"((r)[6]),  "=r"((r)[7]),  \
          "=r"((r)[8]),  "=r"((r)[9]),  "=r"((r)[10]), "=r"((r)[11]), \
          "=r"((r)[12]), "=r"((r)[13]), "=r"((r)[14]), "=r"((r)[15]), \
          "=r"((r)[16]), "=r"((r)[17]), "=r"((r)[18]), "=r"((r)[19]), \
          "=r"((r)[20]), "=r"((r)[21]), "=r"((r)[22]), "=r"((r)[23]), \
          "=r"((r)[24]), "=r"((r)[25]), "=r"((r)[26]), "=r"((r)[27]), \
          "=r"((r)[28]), "=r"((r)[29]), "=r"((r)[30]), "=r"((r)[31]) \
        : "r"(tmem))
#define CP_ASYNC16(smem_u32, gptr) \
    asm volatile("cp.async.cg.shared.global [%0], [%1], 16;" \
        :: "r"((uint32_t)(smem_u32)), "l"(gptr) : "memory")
#define CP_COMMIT() asm volatile("cp.async.commit_group;" ::: "memory")
#define CP_WAIT(n)  asm volatile("cp.async.wait_group %0;" :: "n"(n) : "memory")
// SW128 descriptor: layout=2, version=1(Blackwell), SBO=64, LBO=1
#define SMEM_DESC_BASE_SW128 \
    ((uint64_t(2) << 61) | (uint64_t(1) << 46) | (uint64_t(64) << 32) | (uint64_t(1) << 16))
#define MAKE_SMEM_DESC(addr) (SMEM_DESC_BASE_SW128 | ((uint64_t)((addr) >> 4) & 0x3FFF))
#define SW128(off) ((off) ^ (((off) >> 3) & 0x70))

#if HAS_TCGEN05
__device__ __forceinline__ void mma_f16_ss(uint32_t d_tmem, uint64_t a_desc,
                                           uint64_t b_desc, uint32_t idesc,
                                           bool accum) {
    uint32_t en = accum ? 1u : 0u;
    asm volatile(
        "{\n\t.reg .pred p;\n\tsetp.ne.u32 p, %5, 0;\n\t"
        "tcgen05.mma.cta_group::1.kind::f16 [%0], %1, %2, %3, {%4, %4, %4, %4}, p;\n\t}"
        :: "r"(d_tmem), "l"(a_desc), "l"(b_desc), "r"(idesc), "r"(0u), "r"(en)
        : "memory");
}
#endif

// idesc: dtype F32, atype/btype BF16, M=128; N=128 / 256
#define SIM_IDESC  ((1u << 4) | (1u << 7) | (1u << 10) | ((128u / 8u) << 17) | ((128u / 16u) << 24))
#define GEMM_IDESC ((1u << 4) | (1u << 7) | (1u << 10) | ((256u / 8u) << 17) | ((128u / 16u) << 24))

#if HAS_TCGEN05
// 16 chained K=16 MMAs, K=256, 128x256-bf16 SW128 tiles (16 atom-rows x 4 cols)
__device__ __forceinline__ void issue_tile_mma(uint32_t d_tmem, uint32_t a_smem,
                                               uint32_t b_smem, uint32_t mbar) {
    uint64_t a_base = MAKE_SMEM_DESC(a_smem);
    uint64_t b_base = MAKE_SMEM_DESC(b_smem);
    if (elect_one_pred()) {
        #pragma unroll
        for (int s = 0; s < 16; s++) {
            uint64_t off = (uint64_t)((s >> 2) * 1024 + (s & 3) * 2);
            mma_f16_ss(d_tmem, a_base + off, b_base + off, SIM_IDESC, s > 0);
        }
        TCGEN05_COMMIT(mbar);
    }
}
// 8 chained K=16 MMAs, K=128: A tile 128x128, B tile 256x128, N=256.
__device__ __forceinline__ void g1_issue(uint32_t d_tmem, uint32_t a_smem,
                                         uint32_t b_smem, uint32_t mbar,
                                         bool first_chunk) {
    uint64_t a_base = MAKE_SMEM_DESC(a_smem);
    uint64_t b_base = MAKE_SMEM_DESC(b_smem);
    if (elect_one_pred()) {
        #pragma unroll
        for (int s = 0; s < 8; s++) {
            uint64_t offA = (uint64_t)((s >> 2) * 1024 + (s & 3) * 2);
            uint64_t offB = (uint64_t)((s >> 2) * 2048 + (s & 3) * 2);
            mma_f16_ss(d_tmem, a_base + offA, b_base + offB, GEMM_IDESC,
                       !(first_chunk && s == 0));
        }
        TCGEN05_COMMIT(mbar);
    }
}
// A chunk loader: X[row0..row0+127][k0..k0+127] fp32 -> bf16 SW128 (32 KB)
__device__ __forceinline__ void g1_load_A(const float* __restrict__ X, int row0,
                                          int k0, char* smem, uint32_t A_OFF,
                                          int tid) {
    #pragma unroll
    for (int i = 0; i < 8; i++) {
        int u = tid + i * 256;
        int r = u >> 4, q = u & 15;
        const float* src = X + (size_t)(row0 + r) * DIM + k0 + q * 8;
        float4 v0 = *(const float4*)src;
        float4 v1 = *(const float4*)(src + 4);
        __nv_bfloat162 h[4];
        h[0] = __floats2bfloat162_rn(v0.x, v0.y);
        h[1] = __floats2bfloat162_rn(v0.z, v0.w);
        h[2] = __floats2bfloat162_rn(v1.x, v1.y);
        h[3] = __floats2bfloat162_rn(v1.z, v1.w);
        uint32_t byte_off = (uint32_t)((r >> 3) + ((q >> 3) << 4)) * 1024u
                          + (uint32_t)(r & 7) * 128u + (uint32_t)(q & 7) * 16u;
        *(uint4*)(smem + A_OFF + SW128(byte_off)) = *(uint4*)h;
    }
}
// B chunk loader: Wt[0..255][k0..k0+127] bf16 via cp.async (64 KB)
__device__ __forceinline__ void g1_load_B(const __nv_bfloat16* __restrict__ Wt,
                                          int k0, uint32_t smem_base,
                                          uint32_t B_OFF, int tid) {
    #pragma unroll
    for (int i = 0; i < 16; i++) {
        int u = tid + i * 256;
        int r = u >> 4, q = u & 15;
        uint32_t byte_off = (uint32_t)((r >> 3) + ((q >> 3) << 5)) * 1024u
                          + (uint32_t)(r & 7) * 128u + (uint32_t)(q & 7) * 16u;
        CP_ASYNC16(smem_base + B_OFF + SW128(byte_off),
                   Wt + (size_t)r * DIM + k0 + q * 8);
    }
}
#endif

// ---------------------------------------------------------------------------
// K0: Wt[256,2048] bf16 = transpose(W[2048,256] fp32). 64x64 tiles.
// ---------------------------------------------------------------------------
__global__ void __launch_bounds__(256) k_prep(const float* __restrict__ W,
                                              __nv_bfloat16* __restrict__ Wt)
{
    __shared__ float S[64][68];
    const int k0 = blockIdx.x * 64, n0 = blockIdx.y * 64;
    const int tid = threadIdx.x;

    #pragma unroll
    for (int i = 0; i < 4; i++) {
        int t = tid + i * 256;
        int r = t >> 4, c4 = t & 15;
        float4 v = *(const float4*)&W[(size_t)(k0 + r) * PD + n0 + c4 * 4];
        S[r][c4 * 4 + 0] = v.x; S[r][c4 * 4 + 1] = v.y;
        S[r][c4 * 4 + 2] = v.z; S[r][c4 * 4 + 3] = v.w;
    }
    __syncthreads();
    #pragma unroll
    for (int i = 0; i < 2; i++) {
        int u = tid + i * 256;
        int n = u >> 3, ku = u & 7;
        __nv_bfloat162 h[4];
        #pragma unroll
        for (int m = 0; m < 4; m++)
            h[m] = __floats2bfloat162_rn(S[ku * 8 + 2 * m][n], S[ku * 8 + 2 * m + 1][n]);
        *(uint4*)&Wt[(size_t)(n0 + n) * DIM + k0 + ku * 8] = *(uint4*)h;
    }
}

// ---------------------------------------------------------------------------
// K1: tcgen05 GEMM1 + bias + fused L2-normalize -> bf16. Double-buffered K=128.
// ---------------------------------------------------------------------------
__global__ void __launch_bounds__(256, 1) k_gemm1_tc(
    const float* __restrict__ X, const __nv_bfloat16* __restrict__ Wt,
    const float* __restrict__ b, __nv_bfloat16* __restrict__ Nh)
{
    extern __shared__ __align__(16) char smem[];
    __shared__ float s_red[128][2];
    __shared__ float s_bias[256];

    const int tid = threadIdx.x;
    const int row0 = blockIdx.x * 128;
    s_bias[tid] = b[tid];

#if HAS_TCGEN05
    const uint32_t smem_base = smem_to_u32(smem);
    const uint32_t aoff = ((smem_base + 1024 + 1023) & ~1023u) - smem_base;
    const uint32_t A_OFF0 = aoff;
    const uint32_t A_OFF1 = aoff + 32768;
    const uint32_t B_OFF0 = aoff + 65536;
    const uint32_t B_OFF1 = aoff + 131072;
    const uint32_t TPTR = 0, MB0 = 16, MB1 = 24;

    if (tid < 32) {
        TCGEN05_ALLOC(smem_base + TPTR, 256);
        TCGEN05_RELINQUISH();
    }
    if (tid == 0) { MBARRIER_INIT(smem_base + MB0, 1); MBARRIER_INIT(smem_base + MB1, 1); }
    __syncthreads();
    uint32_t tmem;
    asm volatile("ld.shared.b32 %0, [%1];" : "=r"(tmem) : "r"(smem_base + TPTR));

    g1_load_B(Wt, 0, smem_base, B_OFF0, tid);
    CP_COMMIT();
    g1_load_A(X, row0, 0, smem, A_OFF0, tid);
    CP_WAIT(0);
    __syncthreads();
    FENCE_PROXY_ASYNC();

    int ph0 = 0, ph1 = 0;
    for (int c = 0; c < 16; c++) {
        const int buf = c & 1;
        if (tid < 32)
            g1_issue(tmem, smem_base + (buf ? A_OFF1 : A_OFF0),
                     smem_base + (buf ? B_OFF1 : B_OFF0),
                     smem_base + (buf ? MB1 : MB0), c == 0);
        if (c + 1 < 16) {
            if (c >= 1) {
                if (buf) { MBARRIER_WAIT_PARITY(smem_base + MB0, ph0); ph0 ^= 1; }
                else     { MBARRIER_WAIT_PARITY(smem_base + MB1, ph1); ph1 ^= 1; }
            }
            g1_load_B(Wt, (c + 1) * 128, smem_base, buf ? B_OFF0 : B_OFF1, tid);
            CP_COMMIT();
            g1_load_A(X, row0, (c + 1) * 128, smem, buf ? A_OFF0 : A_OFF1, tid);
            CP_WAIT(0);
            __syncthreads();
            FENCE_PROXY_ASYNC();
        }
    }
    MBARRIER_WAIT_PARITY(smem_base + MB1, ph1);
    TCGEN05_FENCE_AFTER();

    const int w = tid >> 5, lane = tid & 31;
    const int row = (w & 3) * 32 + lane;
    const int half = w >> 2;
    const uint32_t tbase = tmem + half * 128;

    float sumsq = 0.f;
    #pragma unroll
    for (int c4 = 0; c4 < 4; c4++) {
        uint32_t r[32];
        TCGEN05_LD_32X32B_X32(r, tbase + c4 * 32);
        TCGEN05_WAIT_LD();
        #pragma unroll
        for (int j = 0; j < 32; j++) {
            float v = __uint_as_float(r[j]) + s_bias[half * 128 + c4 * 32 + j];
            sumsq += v * v;
        }
    }
    s_red[row][half] = sumsq;
    __syncthreads();
    float inv = 1.0f / fmaxf(sqrtf(s_red[row][0] + s_red[row][1]), 1e-12f);

    const size_t gbase = (size_t)(row0 + row) * PD + half * 128;
    #pragma unroll
    for (int c4 = 0; c4 < 4; c4++) {
        uint32_t r[32];
        TCGEN05_LD_32X32B_X32(r, tbase + c4 * 32);
        TCGEN05_WAIT_LD();
        float v[32];
        #pragma unroll
        for (int j = 0; j < 32; j++)
            v[j] = (__uint_as_float(r[j]) + s_bias[half * 128 + c4 * 32 + j]) * inv;
        __nv_bfloat162 hh[16];
        #pragma unroll
        for (int j2 = 0; j2 < 16; j2++)
            hh[j2] = __floats2bfloat162_rn(v[2 * j2], v[2 * j2 + 1]);
        #pragma unroll
        for (int q = 0; q < 4; q++)
            *(uint4*)&Nh[gbase + c4 * 32 + q * 8] = ((uint4*)hh)[q];
    }
    TCGEN05_FENCE_BEFORE();

    __syncthreads();
    if (tid == 0) { MBARRIER_INVAL(smem_base + MB0); MBARRIER_INVAL(smem_base + MB1); }
    __syncthreads();
    if (tid < 32) TCGEN05_DEALLOC(tmem, 256);
#else
    const int row = row0 + (tid & 127);
    if (tid < 128) {
        float sumsq = 0.f;
        for (int n = 0; n < PD; n++) {
            float s = 0.f;
            for (int k = 0; k < DIM; k++)
                s += X[(size_t)row * DIM + k] * __bfloat162float(Wt[(size_t)n * DIM + k]);
            s += s_bias[n];
            sumsq += s * s;
        }
        float inv = 1.0f / fmaxf(sqrtf(sumsq), 1e-12f);
        for (int n = 0; n < PD; n++) {
            float s = 0.f;
            for (int k = 0; k < DIM; k++)
                s += X[(size_t)row * DIM + k] * __bfloat162float(Wt[(size_t)n * DIM + k]);
            Nh[(size_t)row * PD + n] = __float2bfloat16((s + s_bias[n]) * inv);
        }
    }
#endif
}

// ---------------------------------------------------------------------------
// K4: A-resident pipelined sim+exp+rowsum, compare-free fast path.
// Grid (64 bi, 2 bhalf), 256 thr. Special tile per CTA:
//  - diag CTA (bhalf == bi>>5): tile t=bi&31 masks the diagonal exp.
//  - pos CTA (bhalf==1, bi<32): tile t=bi captures raw sim[gi][gi+4096] -> pos.
// All other tiles: unconditional exp+accumulate (no compares).
// ---------------------------------------------------------------------------
__global__ void __launch_bounds__(256, 1) k_sim_rows(
    const __nv_bfloat16* __restrict__ Nh, float* __restrict__ part,
    float* __restrict__ pos)
{
    extern __shared__ __align__(16) char smem[];
    __shared__ float s_red[128][2];
    const int tid = threadIdx.x;
    const int bi = blockIdx.x, bhalf = blockIdx.y;
    const int ro = bi * 128;

#if HAS_TCGEN05
    const uint32_t smem_base = smem_to_u32(smem);
    const uint32_t aoff = ((smem_base + 1024 + 1023) & ~1023u) - smem_base;
    const uint32_t A_OFF = aoff;
    const uint32_t B_OFF0 = aoff + 65536;
    const uint32_t B_OFF1 = aoff + 131072;
    const uint32_t TPTR = 0, MBAR0 = 16, MBAR1 = 24;

    if (tid < 32) {
        TCGEN05_ALLOC(smem_base + TPTR, 256);
        TCGEN05_RELINQUISH();
    }
    if (tid == 0) { MBARRIER_INIT(smem_base + MBAR0, 1); MBARRIER_INIT(smem_base + MBAR1, 1); }
    __syncthreads();
    uint32_t tmem;
    asm volatile("ld.shared.b32 %0, [%1];" : "=r"(tmem) : "r"(smem_base + TPTR));
    const uint32_t D0 = tmem, D1 = tmem + 128;

    const __nv_bfloat16* Arows = Nh + (size_t)ro * PD;
    const __nv_bfloat16* Bbase = Nh + (size_t)(bhalf * HALF) * PD;

    // Hoisted addressing: absolute smem dsts for both B buffers + gmem offsets.
    uint32_t dstA[16], dst0[16], dst1[16], goff[16];
    #pragma unroll
    for (int it = 0; it < 16; it++) {
        int idx = tid + it * 256;
        int r = idx >> 5, q = idx & 31;
        uint32_t byte_off = (uint32_t)((r >> 3) + ((q >> 3) << 4)) * 1024u
                          + (uint32_t)(r & 7) * 128u + (uint32_t)(q & 7) * 16u;
        uint32_t sw = SW128(byte_off);
        dstA[it] = smem_base + A_OFF + sw;
        dst0[it] = smem_base + B_OFF0 + sw;
        dst1[it] = smem_base + B_OFF1 + sw;
        goff[it] = (uint32_t)(r * PD + q * 8);
    }

    // Prologue
    #pragma unroll
    for (int it = 0; it < 16; it++) {
        CP_ASYNC16(dstA[it], Arows + goff[it]);
        CP_ASYNC16(dst0[it], Bbase + goff[it]);
    }
    CP_COMMIT();
    #pragma unroll
    for (int it = 0; it < 16; it++)
        CP_ASYNC16(dst1[it], Bbase + 128 * PD + goff[it]);
    CP_COMMIT();
    CP_WAIT(1);
    __syncthreads();
    FENCE_PROXY_ASYNC();

    if (tid < 32) issue_tile_mma(D0, smem_base + A_OFF, smem_base + B_OFF0,
                                 smem_base + MBAR0);

    // Epilogue mapping: warp w -> rows (w&3)*32+lane, col half w>>2 (64 cols)
    const int w = tid >> 5, lane = tid & 31;
    const int row = (w & 3) * 32 + lane;
    const int chalf = w >> 2;
    const int gi = ro + row;

    // Special tile per CTA
    const bool sp_diag = (bhalf == (bi >> 5));
    const int t_sp = sp_diag ? (bi & 31) : ((bhalf == 1 && bi < 32) ? bi : -1);
    // special global column for this thread (diag: gi; pos: gi+4096)
    const int sp_col = sp_diag ? gi : gi + HALF;

    int ph0 = 0, ph1 = 0;
    float acc0 = 0.f, acc1 = 0.f;
    float posval = 0.f;

    for (int t = 0; t < 32; t++) {
        const int buf = t & 1;
        const uint32_t mb = smem_base + (buf ? MBAR1 : MBAR0);

        if (buf) { MBARRIER_WAIT_PARITY(mb, ph1); ph1 ^= 1; }
        else     { MBARRIER_WAIT_PARITY(mb, ph0); ph0 ^= 1; }

        if (t + 2 < 32) {
            const __nv_bfloat16* Brows = Bbase + (size_t)(t + 2) * 128 * PD;
            #pragma unroll
            for (int it = 0; it < 16; it++)
                CP_ASYNC16(buf ? dst1[it] : dst0[it], Brows + goff[it]);
        }
        CP_COMMIT();
        CP_WAIT(1);
        __syncthreads();
        FENCE_PROXY_ASYNC();
        TCGEN05_FENCE_AFTER();

        if (t + 1 < 32 && tid < 32)
            issue_tile_mma(buf ? D0 : D1, smem_base + A_OFF,
                           smem_base + (buf ? B_OFF0 : B_OFF1),
                           smem_base + (buf ? MBAR0 : MBAR1));

        const uint32_t dt = (buf ? D1 : D0) + chalf * 64;
        if (t != t_sp) {
            // fast path: no compares
            #pragma unroll
            for (int c4 = 0; c4 < 2; c4++) {
                uint32_t r[32];
                TCGEN05_LD_32X32B_X32(r, dt + c4 * 32);
                TCGEN05_WAIT_LD();
                #pragma unroll
                for (int j = 0; j < 32; j += 2) {
                    acc0 += __expf(10.0f * __uint_as_float(r[j]));
                    acc1 += __expf(10.0f * __uint_as_float(r[j + 1]));
                }
            }
        } else if (sp_diag) {
            const int jb = bhalf * HALF + t * 128 + chalf * 64;
            #pragma unroll
            for (int c4 = 0; c4 < 2; c4++) {
                uint32_t r[32];
                TCGEN05_LD_32X32B_X32(r, dt + c4 * 32);
                TCGEN05_WAIT_LD();
                #pragma unroll
                for (int j = 0; j < 32; j++) {
                    float e = __expf(10.0f * __uint_as_float(r[j]));
                    acc0 += (sp_col == jb + c4 * 32 + j) ? 0.0f : e;
                }
            }
        } else {
            // pos capture tile: accumulate all, capture raw dot at sp_col
            const int jb = bhalf * HALF + t * 128 + chalf * 64;
            #pragma unroll
            for (int c4 = 0; c4 < 2; c4++) {
                uint32_t r[32];
                TCGEN05_LD_32X32B_X32(r, dt + c4 * 32);
                TCGEN05_WAIT_LD();
                #pragma unroll
                for (int j = 0; j < 32; j++) {
                    float v = __uint_as_float(r[j]);
                    acc0 += __expf(10.0f * v);
                    if (sp_col == jb + c4 * 32 + j) posval = v;
                }
            }
        }
        TCGEN05_FENCE_BEFORE();
    }

    // pos write: owner thread of column (gi+4096) is chalf == row>>6
    if (t_sp >= 0 && !sp_diag && (row >> 6) == chalf)
        pos[gi] = posval;

    s_red[row][chalf] = acc0 + acc1;
    __syncthreads();
    if (tid < 128)
        part[(size_t)bhalf * NROWS + ro + tid] = s_red[tid][0] + s_red[tid][1];

    __syncthreads();
    if (tid == 0) { MBARRIER_INVAL(smem_base + MBAR0); MBARRIER_INVAL(smem_base + MBAR1); }
    __syncthreads();
    if (tid < 32) TCGEN05_DEALLOC(tmem, 256);
#else
    // SIMT fallback (compile-only for the portable PTX pass)
    if (tid < 128) {
        const int gi = ro + tid;
        const __nv_bfloat16* arow = Nh + (size_t)gi * PD;
        float rowsum = 0.f;
        for (int j = 0; j < HALF; j++) {
            int gj = bhalf * HALF + j;
            const __nv_bfloat16* brow = Nh + (size_t)gj * PD;
            float s = 0.f;
            for (int k = 0; k < PD; k++)
                s += __bfloat162float(arow[k]) * __bfloat162float(brow[k]);
            rowsum += (gi == gj) ? 0.0f : __expf(10.0f * s);
        }
        part[(size_t)bhalf * NROWS + gi] = rowsum;
        if (bhalf == 1 && bi < 32) {
            const __nv_bfloat16* brow = Nh + (size_t)(gi + HALF) * PD;
            float s = 0.f;
            for (int k = 0; k < PD; k++)
                s += __bfloat162float(arow[k]) * __bfloat162float(brow[k]);
            pos[gi] = s;
        }
    }
#endif
}

// ---------------------------------------------------------------------------
// K6: loss = (sum log(part0+part1) - 20 * sum pos) / 8192
// ---------------------------------------------------------------------------
__global__ void __launch_bounds__(256) k_loss(const float* __restrict__ part,
                                              const float* __restrict__ pos,
                                              float* __restrict__ out)
{
    __shared__ float sh[256];
    float s = 0.f;
    for (int i = threadIdx.x; i < NROWS; i += 256)
        s += logf(part[i] + part[NROWS + i]);
    float p = 0.f;
    for (int i = threadIdx.x; i < HALF; i += 256) p += pos[i];

    sh[threadIdx.x] = s;
    __syncthreads();
    #pragma unroll
    for (int o = 128; o > 0; o >>= 1) {
        if (threadIdx.x < o) sh[threadIdx.x] += sh[threadIdx.x + o];
        __syncthreads();
    }
    float sumlog = sh[0];
    __syncthreads();
    sh[threadIdx.x] = p;
    __syncthreads();
    #pragma unroll
    for (int o = 128; o > 0; o >>= 1) {
        if (threadIdx.x < o) sh[threadIdx.x] += sh[threadIdx.x + o];
        __syncthreads();
    }
    if (threadIdx.x == 0)
        out[0] = (sumlog - 20.0f * sh[0]) / (float)NROWS;
}

// ---------------------------------------------------------------------------
extern "C" void kernel_launch(void* const* d_in, const int* in_sizes, int n_in,
                              void* d_out, int out_size)
{
    const float* X = (const float*)d_in[0];  // [8192, 2048]
    const float* W = (const float*)d_in[1];  // [2048, 256]
    const float* b = (const float*)d_in[2];  // [256]
    float* out = (float*)d_out;

    __nv_bfloat16* nrh;  cudaGetSymbolAddress((void**)&nrh,  g_normh);
    __nv_bfloat16* wt;   cudaGetSymbolAddress((void**)&wt,   g_Wt);
    float* part;         cudaGetSymbolAddress((void**)&part, g_part);
    float* pos;          cudaGetSymbolAddress((void**)&pos,  g_pos);

    const int SIM_SMEM  = 2048 + 3 * 65536;             // 198656 B
    const int GEMM_SMEM = 2048 + 2 * 32768 + 2 * 65536; // 198656 B
    cudaFuncSetAttribute(k_sim_rows,
                         cudaFuncAttributeMaxDynamicSharedMemorySize, SIM_SMEM);
    cudaFuncSetAttribute(k_gemm1_tc,
                         cudaFuncAttributeMaxDynamicSharedMemorySize, GEMM_SMEM);

    k_prep<<<dim3(32, 4), 256>>>(W, wt);
    k_gemm1_tc<<<64, 256, GEMM_SMEM>>>(X, wt, b, nrh);
    k_sim_rows<<<dim3(64, 2), 256, SIM_SMEM>>>(nrh, part, pos);
    k_loss<<<1, 256>>>(part, pos, out);
}

// round 12
// speedup vs baseline: 9.5955x; 1.0476x over previous
#include <cuda_runtime.h>
#include <cuda_bf16.h>
#include <math.h>
#include <cstdint>

// Problem constants
#define NROWS 8192
#define HALF  4096
#define DIM   2048
#define PD    256
#define NT    64

// Feature gate: tcgen05 exists only in the arch-specific sm_103a/sm_100a SASS
// pass. The portable compute_103 PTX pass gets a SIMT fallback (never run).
#if !defined(__CUDA_ARCH__) || defined(__CUDA_ARCH_FEAT_SM103_ALL) || defined(__CUDA_ARCH_FEAT_SM100_ALL)
#define HAS_TCGEN05 1
#else
#define HAS_TCGEN05 0
#endif

// Scratch (device globals; no allocation allowed)
__device__ __nv_bfloat16 g_normh[NROWS * PD];   // bf16 normalized (4 MB)
__device__ __nv_bfloat16 g_Wt[PD * DIM];        // W^T bf16 [256,2048] (1 MB)
__device__ float         g_part[2 * NROWS];     // per-col-half row sums
__device__ float         g_pos[HALF];
__device__ float         g_lred[64];            // per-block log partials
__device__ float         g_ppart[64];           // per-block pos partials
__device__ unsigned int  g_ctr;                 // completion ticket (self-reset)

// ---------------------------------------------------------------------------
// PTX helpers
// ---------------------------------------------------------------------------
__device__ __forceinline__ uint32_t smem_to_u32(const void* p) {
    uint32_t a;
    asm("{ .reg .u64 t; cvta.to.shared.u64 t, %1; cvt.u32.u64 %0, t; }"
        : "=r"(a) : "l"(p));
    return a;
}
__device__ __forceinline__ uint32_t elect_one_pred() {
    uint32_t pred;
    asm volatile("{\n\t.reg .pred p;\n\telect.sync _|p, 0xFFFFFFFF;\n\t"
                 "selp.b32 %0, 1, 0, p;\n\t}" : "=r"(pred));
    return pred;
}
#define TCGEN05_ALLOC(smem_addr, nCols) \
    asm volatile("tcgen05.alloc.cta_group::1.sync.aligned.shared::cta.b32 [%0], %1;" \
        :: "r"((uint32_t)(smem_addr)), "r"((uint32_t)(nCols)) : "memory")
#define TCGEN05_DEALLOC(tmem, nCols) \
    asm volatile("tcgen05.dealloc.cta_group::1.sync.aligned.b32 %0, %1;" \
        :: "r"(tmem), "r"((uint32_t)(nCols)))
#define TCGEN05_RELINQUISH() \
    asm volatile("tcgen05.relinquish_alloc_permit.cta_group::1.sync.aligned;")
#define TCGEN05_COMMIT(mbar) \
    asm volatile("tcgen05.commit.cta_group::1.mbarrier::arrive::one.shared::cluster.b64 [%0];" \
        :: "r"((uint32_t)(mbar)) : "memory")
#define TCGEN05_WAIT_LD()  asm volatile("tcgen05.wait::ld.sync.aligned;" ::: "memory")
#define TCGEN05_FENCE_BEFORE() asm volatile("tcgen05.fence::before_thread_sync;" ::: "memory")
#define TCGEN05_FENCE_AFTER()  asm volatile("tcgen05.fence::after_thread_sync;" ::: "memory")
#define FENCE_PROXY_ASYNC() asm volatile("fence.proxy.async.shared::cta;" ::: "memory")
#define MBARRIER_INIT(mbar, cnt) \
    asm volatile("mbarrier.init.shared.b64 [%0], %1;" \
        :: "r"((uint32_t)(mbar)), "r"((uint32_t)(cnt)) : "memory")
#define MBARRIER_INVAL(mbar) \
    asm volatile("mbarrier.inval.shared.b64 [%0];" :: "r"((uint32_t)(mbar)) : "memory")
#define MBARRIER_WAIT_PARITY(mbar, par) do {                                     \
    uint32_t _m = (uint32_t)(mbar), _p = (uint32_t)(par), _d;                    \
    asm volatile("{\n\t.reg .pred p;\n\t"                                        \
        "mbarrier.try_wait.parity.acquire.cta.shared::cta.b64 p, [%1], %2;\n\t"  \
        "selp.b32 %0, 1, 0, p;\n\t}" : "=r"(_d) : "r"(_m), "r"(_p) : "memory");  \
    if (!_d) {                                                                   \
        asm volatile("{\n\t.reg .pred P1;\n\tWL_%=:\n\t"                         \
            "mbarrier.try_wait.parity.acquire.cta.shared::cta.b64 P1, [%0], %1, 0x989680;\n\t" \
            "@P1 bra.uni WD_%=;\n\tbra.uni WL_%=;\n\tWD_%=:\n\t}"                \
            :: "r"(_m), "r"(_p) : "memory");                                     \
    } } while (0)
#define TCGEN05_LD_32X32B_X32(r, tmem) \
    asm volatile("tcgen05.ld.sync.aligned.32x32b.x32.b32 " \
        "{%0, %1, %2, %3, %4, %5, %6, %7, %8, %9, %10, %11, %12, %13, %14, %15, " \
        "%16, %17, %18, %19, %20, %21, %22, %23, %24, %25, %26, %27, %28, %29, %30, %31}, [%32];" \
        : "=r"((r)[0]),  "=r"((r)[1]),  "=r"((r)[2]),  "=r"((r)[3]),  \
          "=r"((r)[4]),  "=r"((r)[5]),  "=r"((r)[6]),  "=r"((r)[7]),  \
          "=r"((r)[8]),  "=r"((r)[9]),  "=r"((r)[10]), "=r"((r)[11]), \
          "=r"((r)[12]), "=r"((r)[13]), "=r"((r)[14]), "=r"((r)[15]), \
          "=r"((r)[16]), "=r"((r)[17]), "=r"((r)[18]), "=r"((r)[19]), \
          "=r"((r)[20]), "=r"((r)[21]), "=r"((r)[22]), "=r"((r)[23]), \
          "=r"((r)[24]), "=r"((r)[25]), "=r"((r)[26]), "=r"((r)[27]), \
          "=r"((r)[28]), "=r"((r)[29]), "=r"((r)[30]), "=r"((r)[31]) \
        : "r"(tmem))
#define CP_ASYNC16(smem_u32, gptr) \
    asm volatile("cp.async.cg.shared.global [%0], [%1], 16;" \
        :: "r"((uint32_t)(smem_u32)), "l"(gptr) : "memory")
#define CP_COMMIT() asm volatile("cp.async.commit_group;" ::: "memory")
#define CP_WAIT(n)  asm volatile("cp.async.wait_group %0;" :: "n"(n) : "memory")
// SW128 descriptor: layout=2, version=1(Blackwell), SBO=64, LBO=1
#define SMEM_DESC_BASE_SW128 \
    ((uint64_t(2) << 61) | (uint64_t(1) << 46) | (uint64_t(64) << 32) | (uint64_t(1) << 16))
#define MAKE_SMEM_DESC(addr) (SMEM_DESC_BASE_SW128 | ((uint64_t)((addr) >> 4) & 0x3FFF))
#define SW128(off) ((off) ^ (((off) >> 3) & 0x70))

#if HAS_TCGEN05
__device__ __forceinline__ void mma_f16_ss(uint32_t d_tmem, uint64_t a_desc,
                                           uint64_t b_desc, uint32_t idesc,
                                           bool accum) {
    uint32_t en = accum ? 1u : 0u;
    asm volatile(
        "{\n\t.reg .pred p;\n\tsetp.ne.u32 p, %5, 0;\n\t"
        "tcgen05.mma.cta_group::1.kind::f16 [%0], %1, %2, %3, {%4, %4, %4, %4}, p;\n\t}"
        :: "r"(d_tmem), "l"(a_desc), "l"(b_desc), "r"(idesc), "r"(0u), "r"(en)
        : "memory");
}
#endif

// idesc: dtype F32, atype/btype BF16, M=128; N=128 / 256
#define SIM_IDESC  ((1u << 4) | (1u << 7) | (1u << 10) | ((128u / 8u) << 17) | ((128u / 16u) << 24))
#define GEMM_IDESC ((1u << 4) | (1u << 7) | (1u << 10) | ((256u / 8u) << 17) | ((128u / 16u) << 24))

#if HAS_TCGEN05
// 16 chained K=16 MMAs, K=256, 128x256-bf16 SW128 tiles (16 atom-rows x 4 cols)
__device__ __forceinline__ void issue_tile_mma(uint32_t d_tmem, uint32_t a_smem,
                                               uint32_t b_smem, uint32_t mbar) {
    uint64_t a_base = MAKE_SMEM_DESC(a_smem);
    uint64_t b_base = MAKE_SMEM_DESC(b_smem);
    if (elect_one_pred()) {
        #pragma unroll
        for (int s = 0; s < 16; s++) {
            uint64_t off = (uint64_t)((s >> 2) * 1024 + (s & 3) * 2);
            mma_f16_ss(d_tmem, a_base + off, b_base + off, SIM_IDESC, s > 0);
        }
        TCGEN05_COMMIT(mbar);
    }
}
// 8 chained K=16 MMAs, K=128: A tile 128x128, B tile 256x128, N=256.
__device__ __forceinline__ void g1_issue(uint32_t d_tmem, uint32_t a_smem,
                                         uint32_t b_smem, uint32_t mbar,
                                         bool first_chunk) {
    uint64_t a_base = MAKE_SMEM_DESC(a_smem);
    uint64_t b_base = MAKE_SMEM_DESC(b_smem);
    if (elect_one_pred()) {
        #pragma unroll
        for (int s = 0; s < 8; s++) {
            uint64_t offA = (uint64_t)((s >> 2) * 1024 + (s & 3) * 2);
            uint64_t offB = (uint64_t)((s >> 2) * 2048 + (s & 3) * 2);
            mma_f16_ss(d_tmem, a_base + offA, b_base + offB, GEMM_IDESC,
                       !(first_chunk && s == 0));
        }
        TCGEN05_COMMIT(mbar);
    }
}
// A chunk loader: X[row0..row0+127][k0..k0+127] fp32 -> bf16 SW128 (32 KB)
__device__ __forceinline__ void g1_load_A(const float* __restrict__ X, int row0,
                                          int k0, char* smem, uint32_t A_OFF,
                                          int tid) {
    #pragma unroll
    for (int i = 0; i < 8; i++) {
        int u = tid + i * 256;
        int r = u >> 4, q = u & 15;
        const float* src = X + (size_t)(row0 + r) * DIM + k0 + q * 8;
        float4 v0 = *(const float4*)src;
        float4 v1 = *(const float4*)(src + 4);
        __nv_bfloat162 h[4];
        h[0] = __floats2bfloat162_rn(v0.x, v0.y);
        h[1] = __floats2bfloat162_rn(v0.z, v0.w);
        h[2] = __floats2bfloat162_rn(v1.x, v1.y);
        h[3] = __floats2bfloat162_rn(v1.z, v1.w);
        uint32_t byte_off = (uint32_t)((r >> 3) + ((q >> 3) << 4)) * 1024u
                          + (uint32_t)(r & 7) * 128u + (uint32_t)(q & 7) * 16u;
        *(uint4*)(smem + A_OFF + SW128(byte_off)) = *(uint4*)h;
    }
}
// B chunk loader: Wt[0..255][k0..k0+127] bf16 via cp.async (64 KB)
__device__ __forceinline__ void g1_load_B(const __nv_bfloat16* __restrict__ Wt,
                                          int k0, uint32_t smem_base,
                                          uint32_t B_OFF, int tid) {
    #pragma unroll
    for (int i = 0; i < 16; i++) {
        int u = tid + i * 256;
        int r = u >> 4, q = u & 15;
        uint32_t byte_off = (uint32_t)((r >> 3) + ((q >> 3) << 5)) * 1024u
                          + (uint32_t)(r & 7) * 128u + (uint32_t)(q & 7) * 16u;
        CP_ASYNC16(smem_base + B_OFF + SW128(byte_off),
                   Wt + (size_t)r * DIM + k0 + q * 8);
    }
}
#endif

// ---------------------------------------------------------------------------
// K0: Wt[256,2048] bf16 = transpose(W[2048,256] fp32). 64x64 tiles.
// ---------------------------------------------------------------------------
__global__ void __launch_bounds__(256) k_prep(const float* __restrict__ W,
                                              __nv_bfloat16* __restrict__ Wt)
{
    __shared__ float S[64][68];
    const int k0 = blockIdx.x * 64, n0 = blockIdx.y * 64;
    const int tid = threadIdx.x;

    #pragma unroll
    for (int i = 0; i < 4; i++) {
        int t = tid + i * 256;
        int r = t >> 4, c4 = t & 15;
        float4 v = *(const float4*)&W[(size_t)(k0 + r) * PD + n0 + c4 * 4];
        S[r][c4 * 4 + 0] = v.x; S[r][c4 * 4 + 1] = v.y;
        S[r][c4 * 4 + 2] = v.z; S[r][c4 * 4 + 3] = v.w;
    }
    __syncthreads();
    #pragma unroll
    for (int i = 0; i < 2; i++) {
        int u = tid + i * 256;
        int n = u >> 3, ku = u & 7;
        __nv_bfloat162 h[4];
        #pragma unroll
        for (int m = 0; m < 4; m++)
            h[m] = __floats2bfloat162_rn(S[ku * 8 + 2 * m][n], S[ku * 8 + 2 * m + 1][n]);
        *(uint4*)&Wt[(size_t)(n0 + n) * DIM + k0 + ku * 8] = *(uint4*)h;
    }
}

// ---------------------------------------------------------------------------
// K1: tcgen05 GEMM1 + bias + fused L2-normalize -> bf16. Double-buffered K=128.
// ---------------------------------------------------------------------------
__global__ void __launch_bounds__(256, 1) k_gemm1_tc(
    const float* __restrict__ X, const __nv_bfloat16* __restrict__ Wt,
    const float* __restrict__ b, __nv_bfloat16* __restrict__ Nh)
{
    extern __shared__ __align__(16) char smem[];
    __shared__ float s_red[128][2];
    __shared__ float s_bias[256];

    const int tid = threadIdx.x;
    const int row0 = blockIdx.x * 128;
    s_bias[tid] = b[tid];

#if HAS_TCGEN05
    const uint32_t smem_base = smem_to_u32(smem);
    const uint32_t aoff = ((smem_base + 1024 + 1023) & ~1023u) - smem_base;
    const uint32_t A_OFF0 = aoff;
    const uint32_t A_OFF1 = aoff + 32768;
    const uint32_t B_OFF0 = aoff + 65536;
    const uint32_t B_OFF1 = aoff + 131072;
    const uint32_t TPTR = 0, MB0 = 16, MB1 = 24;

    if (tid < 32) {
        TCGEN05_ALLOC(smem_base + TPTR, 256);
        TCGEN05_RELINQUISH();
    }
    if (tid == 0) { MBARRIER_INIT(smem_base + MB0, 1); MBARRIER_INIT(smem_base + MB1, 1); }
    __syncthreads();
    uint32_t tmem;
    asm volatile("ld.shared.b32 %0, [%1];" : "=r"(tmem) : "r"(smem_base + TPTR));

    g1_load_B(Wt, 0, smem_base, B_OFF0, tid);
    CP_COMMIT();
    g1_load_A(X, row0, 0, smem, A_OFF0, tid);
    CP_WAIT(0);
    __syncthreads();
    FENCE_PROXY_ASYNC();

    int ph0 = 0, ph1 = 0;
    for (int c = 0; c < 16; c++) {
        const int buf = c & 1;
        if (tid < 32)
            g1_issue(tmem, smem_base + (buf ? A_OFF1 : A_OFF0),
                     smem_base + (buf ? B_OFF1 : B_OFF0),
                     smem_base + (buf ? MB1 : MB0), c == 0);
        if (c + 1 < 16) {
            if (c >= 1) {
                if (buf) { MBARRIER_WAIT_PARITY(smem_base + MB0, ph0); ph0 ^= 1; }
                else     { MBARRIER_WAIT_PARITY(smem_base + MB1, ph1); ph1 ^= 1; }
            }
            g1_load_B(Wt, (c + 1) * 128, smem_base, buf ? B_OFF0 : B_OFF1, tid);
            CP_COMMIT();
            g1_load_A(X, row0, (c + 1) * 128, smem, buf ? A_OFF0 : A_OFF1, tid);
            CP_WAIT(0);
            __syncthreads();
            FENCE_PROXY_ASYNC();
        }
    }
    MBARRIER_WAIT_PARITY(smem_base + MB1, ph1);
    TCGEN05_FENCE_AFTER();

    const int w = tid >> 5, lane = tid & 31;
    const int row = (w & 3) * 32 + lane;
    const int half = w >> 2;
    const uint32_t tbase = tmem + half * 128;

    float sumsq = 0.f;
    #pragma unroll
    for (int c4 = 0; c4 < 4; c4++) {
        uint32_t r[32];
        TCGEN05_LD_32X32B_X32(r, tbase + c4 * 32);
        TCGEN05_WAIT_LD();
        #pragma unroll
        for (int j = 0; j < 32; j++) {
            float v = __uint_as_float(r[j]) + s_bias[half * 128 + c4 * 32 + j];
            sumsq += v * v;
        }
    }
    s_red[row][half] = sumsq;
    __syncthreads();
    float inv = 1.0f / fmaxf(sqrtf(s_red[row][0] + s_red[row][1]), 1e-12f);

    const size_t gbase = (size_t)(row0 + row) * PD + half * 128;
    #pragma unroll
    for (int c4 = 0; c4 < 4; c4++) {
        uint32_t r[32];
        TCGEN05_LD_32X32B_X32(r, tbase + c4 * 32);
        TCGEN05_WAIT_LD();
        float v[32];
        #pragma unroll
        for (int j = 0; j < 32; j++)
            v[j] = (__uint_as_float(r[j]) + s_bias[half * 128 + c4 * 32 + j]) * inv;
        __nv_bfloat162 hh[16];
        #pragma unroll
        for (int j2 = 0; j2 < 16; j2++)
            hh[j2] = __floats2bfloat162_rn(v[2 * j2], v[2 * j2 + 1]);
        #pragma unroll
        for (int q = 0; q < 4; q++)
            *(uint4*)&Nh[gbase + c4 * 32 + q * 8] = ((uint4*)hh)[q];
    }
    TCGEN05_FENCE_BEFORE();

    __syncthreads();
    if (tid == 0) { MBARRIER_INVAL(smem_base + MB0); MBARRIER_INVAL(smem_base + MB1); }
    __syncthreads();
    if (tid < 32) TCGEN05_DEALLOC(tmem, 256);
#else
    const int row = row0 + (tid & 127);
    if (tid < 128) {
        float sumsq = 0.f;
        for (int n = 0; n < PD; n++) {
            float s = 0.f;
            for (int k = 0; k < DIM; k++)
                s += X[(size_t)row * DIM + k] * __bfloat162float(Wt[(size_t)n * DIM + k]);
            s += s_bias[n];
            sumsq += s * s;
        }
        float inv = 1.0f / fmaxf(sqrtf(sumsq), 1e-12f);
        for (int n = 0; n < PD; n++) {
            float s = 0.f;
            for (int k = 0; k < DIM; k++)
                s += X[(size_t)row * DIM + k] * __bfloat162float(Wt[(size_t)n * DIM + k]);
            Nh[(size_t)row * PD + n] = __float2bfloat16((s + s_bias[n]) * inv);
        }
    }
#endif
}

// ---------------------------------------------------------------------------
// K4: A-resident pipelined sim+exp+rowsum, compare-free fast path.
// Grid (64 bi, 2 bhalf), 256 thr. Special tile per CTA:
//  - diag CTA (bhalf == bi>>5): tile t=bi&31 masks the diagonal exp.
//  - pos CTA (bhalf==1, bi<32): tile t=bi captures raw sim[gi][gi+4096] -> pos.
// ---------------------------------------------------------------------------
__global__ void __launch_bounds__(256, 1) k_sim_rows(
    const __nv_bfloat16* __restrict__ Nh, float* __restrict__ part,
    float* __restrict__ pos)
{
    extern __shared__ __align__(16) char smem[];
    __shared__ float s_red[128][2];
    const int tid = threadIdx.x;
    const int bi = blockIdx.x, bhalf = blockIdx.y;
    const int ro = bi * 128;

#if HAS_TCGEN05
    const uint32_t smem_base = smem_to_u32(smem);
    const uint32_t aoff = ((smem_base + 1024 + 1023) & ~1023u) - smem_base;
    const uint32_t A_OFF = aoff;
    const uint32_t B_OFF0 = aoff + 65536;
    const uint32_t B_OFF1 = aoff + 131072;
    const uint32_t TPTR = 0, MBAR0 = 16, MBAR1 = 24;

    if (tid < 32) {
        TCGEN05_ALLOC(smem_base + TPTR, 256);
        TCGEN05_RELINQUISH();
    }
    if (tid == 0) { MBARRIER_INIT(smem_base + MBAR0, 1); MBARRIER_INIT(smem_base + MBAR1, 1); }
    __syncthreads();
    uint32_t tmem;
    asm volatile("ld.shared.b32 %0, [%1];" : "=r"(tmem) : "r"(smem_base + TPTR));
    const uint32_t D0 = tmem, D1 = tmem + 128;

    const __nv_bfloat16* Arows = Nh + (size_t)ro * PD;
    const __nv_bfloat16* Bbase = Nh + (size_t)(bhalf * HALF) * PD;

    // Hoisted addressing: absolute smem dsts for both B buffers + gmem offsets.
    uint32_t dstA[16], dst0[16], dst1[16], goff[16];
    #pragma unroll
    for (int it = 0; it < 16; it++) {
        int idx = tid + it * 256;
        int r = idx >> 5, q = idx & 31;
        uint32_t byte_off = (uint32_t)((r >> 3) + ((q >> 3) << 4)) * 1024u
                          + (uint32_t)(r & 7) * 128u + (uint32_t)(q & 7) * 16u;
        uint32_t sw = SW128(byte_off);
        dstA[it] = smem_base + A_OFF + sw;
        dst0[it] = smem_base + B_OFF0 + sw;
        dst1[it] = smem_base + B_OFF1 + sw;
        goff[it] = (uint32_t)(r * PD + q * 8);
    }

    // Prologue
    #pragma unroll
    for (int it = 0; it < 16; it++) {
        CP_ASYNC16(dstA[it], Arows + goff[it]);
        CP_ASYNC16(dst0[it], Bbase + goff[it]);
    }
    CP_COMMIT();
    #pragma unroll
    for (int it = 0; it < 16; it++)
        CP_ASYNC16(dst1[it], Bbase + 128 * PD + goff[it]);
    CP_COMMIT();
    CP_WAIT(1);
    __syncthreads();
    FENCE_PROXY_ASYNC();

    if (tid < 32) issue_tile_mma(D0, smem_base + A_OFF, smem_base + B_OFF0,
                                 smem_base + MBAR0);

    // Epilogue mapping: warp w -> rows (w&3)*32+lane, col half w>>2 (64 cols)
    const int w = tid >> 5, lane = tid & 31;
    const int row = (w & 3) * 32 + lane;
    const int chalf = w >> 2;
    const int gi = ro + row;

    // Special tile per CTA
    const bool sp_diag = (bhalf == (bi >> 5));
    const int t_sp = sp_diag ? (bi & 31) : ((bhalf == 1 && bi < 32) ? bi : -1);
    const int sp_col = sp_diag ? gi : gi + HALF;

    int ph0 = 0, ph1 = 0;
    float acc0 = 0.f, acc1 = 0.f;
    float posval = 0.f;

    for (int t = 0; t < 32; t++) {
        const int buf = t & 1;
        const uint32_t mb = smem_base + (buf ? MBAR1 : MBAR0);

        if (buf) { MBARRIER_WAIT_PARITY(mb, ph1); ph1 ^= 1; }
        else     { MBARRIER_WAIT_PARITY(mb, ph0); ph0 ^= 1; }

        if (t + 2 < 32) {
            const __nv_bfloat16* Brows = Bbase + (size_t)(t + 2) * 128 * PD;
            #pragma unroll
            for (int it = 0; it < 16; it++)
                CP_ASYNC16(buf ? dst1[it] : dst0[it], Brows + goff[it]);
        }
        CP_COMMIT();
        CP_WAIT(1);
        __syncthreads();
        FENCE_PROXY_ASYNC();
        TCGEN05_FENCE_AFTER();

        if (t + 1 < 32 && tid < 32)
            issue_tile_mma(buf ? D0 : D1, smem_base + A_OFF,
                           smem_base + (buf ? B_OFF0 : B_OFF1),
                           smem_base + (buf ? MBAR0 : MBAR1));

        const uint32_t dt = (buf ? D1 : D0) + chalf * 64;
        if (t != t_sp) {
            #pragma unroll
            for (int c4 = 0; c4 < 2; c4++) {
                uint32_t r[32];
                TCGEN05_LD_32X32B_X32(r, dt + c4 * 32);
                TCGEN05_WAIT_LD();
                #pragma unroll
                for (int j = 0; j < 32; j += 2) {
                    acc0 += __expf(10.0f * __uint_as_float(r[j]));
                    acc1 += __expf(10.0f * __uint_as_float(r[j + 1]));
                }
            }
        } else if (sp_diag) {
            const int jb = bhalf * HALF + t * 128 + chalf * 64;
            #pragma unroll
            for (int c4 = 0; c4 < 2; c4++) {
                uint32_t r[32];
                TCGEN05_LD_32X32B_X32(r, dt + c4 * 32);
                TCGEN05_WAIT_LD();
                #pragma unroll
                for (int j = 0; j < 32; j++) {
                    float e = __expf(10.0f * __uint_as_float(r[j]));
                    acc0 += (sp_col == jb + c4 * 32 + j) ? 0.0f : e;
                }
            }
        } else {
            const int jb = bhalf * HALF + t * 128 + chalf * 64;
            #pragma unroll
            for (int c4 = 0; c4 < 2; c4++) {
                uint32_t r[32];
                TCGEN05_LD_32X32B_X32(r, dt + c4 * 32);
                TCGEN05_WAIT_LD();
                #pragma unroll
                for (int j = 0; j < 32; j++) {
                    float v = __uint_as_float(r[j]);
                    acc0 += __expf(10.0f * v);
                    if (sp_col == jb + c4 * 32 + j) posval = v;
                }
            }
        }
        TCGEN05_FENCE_BEFORE();
    }

    if (t_sp >= 0 && !sp_diag && (row >> 6) == chalf)
        pos[gi] = posval;

    s_red[row][chalf] = acc0 + acc1;
    __syncthreads();
    if (tid < 128)
        part[(size_t)bhalf * NROWS + ro + tid] = s_red[tid][0] + s_red[tid][1];

    __syncthreads();
    if (tid == 0) { MBARRIER_INVAL(smem_base + MBAR0); MBARRIER_INVAL(smem_base + MBAR1); }
    __syncthreads();
    if (tid < 32) TCGEN05_DEALLOC(tmem, 256);
#else
    if (tid < 128) {
        const int gi = ro + tid;
        const __nv_bfloat16* arow = Nh + (size_t)gi * PD;
        float rowsum = 0.f;
        for (int j = 0; j < HALF; j++) {
            int gj = bhalf * HALF + j;
            const __nv_bfloat16* brow = Nh + (size_t)gj * PD;
            float s = 0.f;
            for (int k = 0; k < PD; k++)
                s += __bfloat162float(arow[k]) * __bfloat162float(brow[k]);
            rowsum += (gi == gj) ? 0.0f : __expf(10.0f * s);
        }
        part[(size_t)bhalf * NROWS + gi] = rowsum;
        if (bhalf == 1 && bi < 32) {
            const __nv_bfloat16* brow = Nh + (size_t)(gi + HALF) * PD;
            float s = 0.f;
            for (int k = 0; k < PD; k++)
                s += __bfloat162float(arow[k]) * __bfloat162float(brow[k]);
            pos[gi] = s;
        }
    }
#endif
}

// ---------------------------------------------------------------------------
// K6: parallel loss reduction. Grid 64 x 256 threads.
// Block b: 128 rows of log(neg) + 64 pos entries -> fixed partial slots.
// Last-arriving block (atomic ticket) reduces 64 partials in fixed order.
// Counter self-resets for graph replay determinism.
// ---------------------------------------------------------------------------
__global__ void __launch_bounds__(256) k_loss(const float* __restrict__ part,
                                              const float* __restrict__ pos,
                                              float* __restrict__ lred,
                                              float* __restrict__ ppart,
                                              unsigned int* __restrict__ ctr,
                                              float* __restrict__ out)
{
    __shared__ float sh[256];
    __shared__ bool is_last;
    const int b = blockIdx.x;
    const int tid = threadIdx.x;

    // log(neg) over rows b*128 .. b*128+127 (tid<128 active)
    float s = 0.f;
    if (tid < 128) {
        int i = b * 128 + tid;
        s = logf(part[i] + part[NROWS + i]);
    }
    // pos over entries b*64 .. b*64+63 (tid<64 active)
    float p = (tid < 64) ? pos[b * 64 + tid] : 0.f;

    sh[tid] = s;
    __syncthreads();
    #pragma unroll
    for (int o = 128; o > 0; o >>= 1) {
        if (tid < o) sh[tid] += sh[tid + o];
        __syncthreads();
    }
    float lsum = sh[0];
    __syncthreads();
    sh[tid] = p;
    __syncthreads();
    #pragma unroll
    for (int o = 128; o > 0; o >>= 1) {
        if (tid < o) sh[tid] += sh[tid + o];
        __syncthreads();
    }
    if (tid == 0) {
        lred[b]  = lsum;
        ppart[b] = sh[0];
        __threadfence();
        unsigned int old = atomicAdd(ctr, 1u);
        is_last = (old == 63u);
    }
    __syncthreads();

    if (is_last) {
        // final reduction over 64 partials, fixed order
        float lv = (tid < 64) ? lred[tid]  : 0.f;
        float pv = (tid < 64) ? ppart[tid] : 0.f;
        sh[tid] = lv;
        __syncthreads();
        #pragma unroll
        for (int o = 128; o > 0; o >>= 1) {
            if (tid < o) sh[tid] += sh[tid + o];
            __syncthreads();
        }
        float L = sh[0];
        __syncthreads();
        sh[tid] = pv;
        __syncthreads();
        #pragma unroll
        for (int o = 128; o > 0; o >>= 1) {
            if (tid < o) sh[tid] += sh[tid + o];
            __syncthreads();
        }
        if (tid == 0) {
            out[0] = (L - 20.0f * sh[0]) / (float)NROWS;
            *ctr = 0u;   // reset for next graph replay
        }
    }
}

// ---------------------------------------------------------------------------
extern "C" void kernel_launch(void* const* d_in, const int* in_sizes, int n_in,
                              void* d_out, int out_size)
{
    const float* X = (const float*)d_in[0];  // [8192, 2048]
    const float* W = (const float*)d_in[1];  // [2048, 256]
    const float* b = (const float*)d_in[2];  // [256]
    float* out = (float*)d_out;

    __nv_bfloat16* nrh;  cudaGetSymbolAddress((void**)&nrh,   g_normh);
    __nv_bfloat16* wt;   cudaGetSymbolAddress((void**)&wt,    g_Wt);
    float* part;         cudaGetSymbolAddress((void**)&part,  g_part);
    float* pos;          cudaGetSymbolAddress((void**)&pos,   g_pos);
    float* lred;         cudaGetSymbolAddress((void**)&lred,  g_lred);
    float* ppart;        cudaGetSymbolAddress((void**)&ppart, g_ppart);
    unsigned int* ctr;   cudaGetSymbolAddress((void**)&ctr,   g_ctr);

    const int SIM_SMEM  = 2048 + 3 * 65536;             // 198656 B
    const int GEMM_SMEM = 2048 + 2 * 32768 + 2 * 65536; // 198656 B
    cudaFuncSetAttribute(k_sim_rows,
                         cudaFuncAttributeMaxDynamicSharedMemorySize, SIM_SMEM);
    cudaFuncSetAttribute(k_gemm1_tc,
                         cudaFuncAttributeMaxDynamicSharedMemorySize, GEMM_SMEM);

    k_prep<<<dim3(32, 4), 256>>>(W, wt);
    k_gemm1_tc<<<64, 256, GEMM_SMEM>>>(X, wt, b, nrh);
    k_sim_rows<<<dim3(64, 2), 256, SIM_SMEM>>>(nrh, part, pos);
    k_loss<<<64, 256>>>(part, pos, lred, ppart, ctr, out);
}